// round 15
// baseline (speedup 1.0000x reference)
#include <cuda_runtime.h>
#include <math.h>
#include <stdint.h>

#define NN   8192
#define BB   8
#define LL   1024
#define INC  64
#define HH   8
#define CC   32
#define DD   256
#define DFF  2048
#define EMAX 262144
#define ETOTMAX (EMAX + NN)

#define TG_STG   (256 * 36)
#define TG_SMEM2 (2 * TG_STG * 4)        // 73728 B -> 2 CTAs/SM
#define TL_STG   (320 * 36)
#define TL_SMEM3 (3 * TL_STG * 4)

// attention smem (dynamic): Qs 128x36 + Ks 64x36 + Vt 32x68 + Ps 128x68
#define AT_SMEM ((128 * 36 + 64 * 36 + 32 * 68 + 128 * 68) * 4)

// pre-rounded weight scratch sizes (floats)
#define W0_N   (DD * INC)
#define W12_N  (2 * DD * DD)
#define QW_N   (2 * 3 * DD * DD)
#define OW_N   (2 * DD * DD)
#define F1_N   (2 * DFF * DD)
#define F2_N   (2 * DD * DFF)
#define WR_N   (W0_N + W12_N + QW_N + OW_N + F1_N + F2_N)

// ---------------- scratch (device globals; no runtime allocation) ----------------
__device__ float g_hl  [NN * DD];
__device__ float g_h0  [NN * DD];
__device__ float g_h1  [NN * DD];
__device__ float g_as  [NN * HH];
__device__ float g_ad  [NN * HH];
__device__ float g_qkv [NN * 3 * DD];
__device__ float g_attn[NN * DD];
__device__ float g_ff  [NN * DFF];
__device__ float g_wr  [WR_N];
// CSR (built once per launch)
__device__ int   g_deg [NN];
__device__ int   g_off [NN + 1];
__device__ int   g_pos [NN];
__device__ int   g_esrc[ETOTMAX];
__device__ int   g_edst[ETOTMAX];

// ---------------- helpers ----------------
__device__ __forceinline__ float f2tf_f(float f) {
    unsigned u;
    asm("cvt.rna.tf32.f32 %0, %1;" : "=r"(u) : "f"(f));
    return __uint_as_float(u);
}

__device__ __forceinline__ unsigned f2tf_u(float f) {
    unsigned u;
    asm("cvt.rna.tf32.f32 %0, %1;" : "=r"(u) : "f"(f));
    return u;
}

__device__ __forceinline__ void mma8(float* d, const unsigned* a, const unsigned* b) {
    asm volatile(
        "mma.sync.aligned.m16n8k8.row.col.f32.tf32.tf32.f32 "
        "{%0,%1,%2,%3},{%4,%5,%6,%7},{%8,%9},{%0,%1,%2,%3};"
        : "+f"(d[0]), "+f"(d[1]), "+f"(d[2]), "+f"(d[3])
        : "r"(a[0]), "r"(a[1]), "r"(a[2]), "r"(a[3]), "r"(b[0]), "r"(b[1]));
}

#define CP16(dst_u32, src_ptr) \
    asm volatile("cp.async.cg.shared.global [%0], [%1], 16;\n" :: "r"(dst_u32), "l"(src_ptr))
#define CP_COMMIT() asm volatile("cp.async.commit_group;\n" ::)
#define CP_WAIT1()  asm volatile("cp.async.wait_group 1;\n" ::)

// ---------------- merged tf32 pre-round (once per launch, all weights) ----------
__global__ void round_all_kernel(const float* __restrict__ s0, const float* __restrict__ s1,
                                 const float* __restrict__ s2, const float* __restrict__ s3,
                                 const float* __restrict__ s4, const float* __restrict__ s5,
                                 float* __restrict__ dst)
{
    int i = blockIdx.x * blockDim.x + threadIdx.x;   // float4 index
    if (i >= WR_N / 4) return;
    int f = i * 4;
    const float* src;
    int off;
    if (f < W0_N)                                  { src = s0; off = f; }
    else if (f < W0_N + W12_N)                     { src = s1; off = f - W0_N; }
    else if (f < W0_N + W12_N + QW_N)              { src = s2; off = f - (W0_N + W12_N); }
    else if (f < W0_N + W12_N + QW_N + OW_N)       { src = s3; off = f - (W0_N + W12_N + QW_N); }
    else if (f < W0_N + W12_N + QW_N + OW_N + F1_N){ src = s4; off = f - (W0_N + W12_N + QW_N + OW_N); }
    else                                           { src = s5; off = f - (W0_N + W12_N + QW_N + OW_N + F1_N); }
    float4 v = *(const float4*)(src + off);
    v.x = f2tf_f(v.x); v.y = f2tf_f(v.y);
    v.z = f2tf_f(v.z); v.w = f2tf_f(v.w);
    ((float4*)dst)[i] = v;
}

// ---------------- cp.async 2-stage tensor-core GEMM (2 CTAs/SM) -------------------
// BIASMODE: 0 none, 1 bias, 2 bias+relu, 3 GAT (no bias/relu; fused coef dot)
template<int BIASMODE>
__global__ void __launch_bounds__(256, 2) tgemm_kernel(
    const float* __restrict__ A, const float* __restrict__ W,
    const float* __restrict__ bias, float* __restrict__ C,
    int M, int Nn, int K,
    const float* __restrict__ atts, const float* __restrict__ attd,
    float* __restrict__ asv, float* __restrict__ adv)
{
    extern __shared__ __align__(16) float sm[];
    unsigned sbase = (unsigned)__cvta_generic_to_shared(sm);

    const int bm = blockIdx.y * 128;
    const int bn = blockIdx.x * 128;
    const int tid = threadIdx.x;
    const int warp = tid >> 5, lane = tid & 31;
    const int wm = warp & 3, wn = warp >> 2;
    const int lg = lane >> 2, lt = lane & 3;

    int lrow[4], lc4[4];
#pragma unroll
    for (int i = 0; i < 4; i++) {
        int f4 = tid + i * 256;
        lrow[i] = f4 >> 3;
        lc4[i] = (f4 & 7) << 2;
    }

    float acc[2][8][4];
#pragma unroll
    for (int mt = 0; mt < 2; mt++)
#pragma unroll
        for (int nt = 0; nt < 8; nt++)
#pragma unroll
            for (int r = 0; r < 4; r++) acc[mt][nt][r] = 0.0f;

    const int nk = K >> 5;
    auto issue = [&](int t) {
        if (t < nk) {
            int k0 = t << 5;
            unsigned so = sbase + (unsigned)((t & 1) * TG_STG) * 4u;
#pragma unroll
            for (int i = 0; i < 4; i++) {
                const float* gA = A + (size_t)(bm + lrow[i]) * K + k0 + lc4[i];
                const float* gB = W + (size_t)(bn + lrow[i]) * K + k0 + lc4[i];
                CP16(so + (unsigned)(lrow[i] * 36 + lc4[i]) * 4u, gA);
                CP16(so + (unsigned)((128 * 36) + lrow[i] * 36 + lc4[i]) * 4u, gB);
            }
        }
        CP_COMMIT();
    };

    issue(0);
    for (int t = 0; t < nk; t++) {
        issue(t + 1);
        CP_WAIT1();
        __syncthreads();
        const float* As = sm + (t & 1) * TG_STG;
        const float* Bs = As + 128 * 36;
#pragma unroll
        for (int kk = 0; kk < 32; kk += 8) {
            unsigned ah[2][4], bf[8][2];
            const int c = kk + lt;
#pragma unroll
            for (int mt = 0; mt < 2; mt++) {
                int r = wm * 32 + mt * 16 + lg;
                ah[mt][0] = f2tf_u(As[r * 36 + c]);
                ah[mt][1] = f2tf_u(As[(r + 8) * 36 + c]);
                ah[mt][2] = f2tf_u(As[r * 36 + c + 4]);
                ah[mt][3] = f2tf_u(As[(r + 8) * 36 + c + 4]);
            }
#pragma unroll
            for (int nt = 0; nt < 8; nt++) {
                int n = wn * 64 + nt * 8 + lg;
                bf[nt][0] = __float_as_uint(Bs[n * 36 + c]);
                bf[nt][1] = __float_as_uint(Bs[n * 36 + c + 4]);
            }
#pragma unroll
            for (int mt = 0; mt < 2; mt++)
#pragma unroll
                for (int nt = 0; nt < 8; nt++)
                    mma8(acc[mt][nt], ah[mt], bf[nt]);
        }
        __syncthreads();
    }

    // fused GAT coef partials: [mt][rowhalf][head-in-warp(2)]
    float aS[2][2][2], aD[2][2][2];
    if (BIASMODE == 3) {
#pragma unroll
        for (int a = 0; a < 2; a++)
#pragma unroll
            for (int b2 = 0; b2 < 2; b2++)
#pragma unroll
                for (int c2 = 0; c2 < 2; c2++) { aS[a][b2][c2] = 0.f; aD[a][b2][c2] = 0.f; }
    }

#pragma unroll
    for (int mt = 0; mt < 2; mt++) {
#pragma unroll
        for (int nt = 0; nt < 8; nt++) {
            int row = bm + wm * 32 + mt * 16 + lg;
            int col = bn + wn * 64 + nt * 8 + (lt << 1);
            float b0 = 0.f, b1 = 0.f;
            if (BIASMODE == 1 || BIASMODE == 2) { b0 = bias[col]; b1 = bias[col + 1]; }
            float v0 = acc[mt][nt][0] + b0, v1 = acc[mt][nt][1] + b1;
            float v2 = acc[mt][nt][2] + b0, v3 = acc[mt][nt][3] + b1;
            if (BIASMODE == 2) {
                v0 = fmaxf(v0, 0.f); v1 = fmaxf(v1, 0.f);
                v2 = fmaxf(v2, 0.f); v3 = fmaxf(v3, 0.f);
            }
            if (BIASMODE == 3) {
                int hs = nt >> 2;
                float2 ts = *(const float2*)&atts[col];
                float2 td = *(const float2*)&attd[col];
                aS[mt][0][hs] += v0 * ts.x + v1 * ts.y;
                aS[mt][1][hs] += v2 * ts.x + v3 * ts.y;
                aD[mt][0][hs] += v0 * td.x + v1 * td.y;
                aD[mt][1][hs] += v2 * td.x + v3 * td.y;
            }
            *(float2*)&C[(size_t)row * Nn + col] = make_float2(v0, v1);
            *(float2*)&C[(size_t)(row + 8) * Nn + col] = make_float2(v2, v3);
        }
    }

    if (BIASMODE == 3) {
#pragma unroll
        for (int mt = 0; mt < 2; mt++)
#pragma unroll
            for (int hf = 0; hf < 2; hf++)
#pragma unroll
                for (int hs = 0; hs < 2; hs++) {
                    float s = aS[mt][hf][hs], d = aD[mt][hf][hs];
                    s += __shfl_xor_sync(0xffffffffu, s, 1);
                    s += __shfl_xor_sync(0xffffffffu, s, 2);
                    d += __shfl_xor_sync(0xffffffffu, d, 1);
                    d += __shfl_xor_sync(0xffffffffu, d, 2);
                    aS[mt][hf][hs] = s; aD[mt][hf][hs] = d;
                }
        if (lt == 0) {
            int headbase = (bn + wn * 64) >> 5;
#pragma unroll
            for (int mt = 0; mt < 2; mt++)
#pragma unroll
                for (int hf = 0; hf < 2; hf++) {
                    int row = bm + wm * 32 + mt * 16 + lg + hf * 8;
#pragma unroll
                    for (int hs = 0; hs < 2; hs++) {
                        asv[row * 8 + headbase + hs] = aS[mt][hf][hs];
                        adv[row * 8 + headbase + hs] = aD[mt][hf][hs];
                    }
                }
        }
    }
}

// ---------------- GEMM + residual + LayerNorm fused (BM=64, BN=256, 3-stage) ----
__global__ void __launch_bounds__(256) tgemm_ln_kernel(
    const float* __restrict__ A, const float* __restrict__ W,
    const float* __restrict__ bias, const float* __restrict__ res,
    const float* __restrict__ lnw, const float* __restrict__ lnb,
    float* __restrict__ Y, int M, int K)
{
    extern __shared__ __align__(16) float sm[];
    unsigned sbase = (unsigned)__cvta_generic_to_shared(sm);

    const int bm = blockIdx.y * 64;
    const int tid = threadIdx.x;
    const int warp = tid >> 5, lane = tid & 31;
    const int wm = warp & 1, wn = warp >> 1;
    const int lg = lane >> 2, lt = lane & 3;

    int arow[2], ac4[2], brow[8], bc4[8];
#pragma unroll
    for (int i = 0; i < 2; i++) {
        int f4 = tid + i * 256;
        arow[i] = f4 >> 3; ac4[i] = (f4 & 7) << 2;
    }
#pragma unroll
    for (int i = 0; i < 8; i++) {
        int f4 = tid + i * 256;
        brow[i] = f4 >> 3; bc4[i] = (f4 & 7) << 2;
    }

    float acc[2][8][4];
#pragma unroll
    for (int mt = 0; mt < 2; mt++)
#pragma unroll
        for (int nt = 0; nt < 8; nt++)
#pragma unroll
            for (int r = 0; r < 4; r++) acc[mt][nt][r] = 0.0f;

    const int nk = K >> 5;
    auto issue = [&](int t) {
        if (t < nk) {
            int k0 = t << 5;
            unsigned so = sbase + (unsigned)((t % 3) * TL_STG) * 4u;
#pragma unroll
            for (int i = 0; i < 2; i++) {
                const float* gA = A + (size_t)(bm + arow[i]) * K + k0 + ac4[i];
                CP16(so + (unsigned)(arow[i] * 36 + ac4[i]) * 4u, gA);
            }
#pragma unroll
            for (int i = 0; i < 8; i++) {
                const float* gB = W + (size_t)brow[i] * K + k0 + bc4[i];
                CP16(so + (unsigned)((64 * 36) + brow[i] * 36 + bc4[i]) * 4u, gB);
            }
        }
        CP_COMMIT();
    };

    issue(0); issue(1);
    for (int t = 0; t < nk; t++) {
        CP_WAIT1();
        __syncthreads();
        issue(t + 2);
        const float* As = sm + (t % 3) * TL_STG;
        const float* Bs = As + 64 * 36;
#pragma unroll
        for (int kk = 0; kk < 32; kk += 8) {
            unsigned ah[2][4], bf[8][2];
            const int c = kk + lt;
#pragma unroll
            for (int mt = 0; mt < 2; mt++) {
                int r = wm * 32 + mt * 16 + lg;
                ah[mt][0] = f2tf_u(As[r * 36 + c]);
                ah[mt][1] = f2tf_u(As[(r + 8) * 36 + c]);
                ah[mt][2] = f2tf_u(As[r * 36 + c + 4]);
                ah[mt][3] = f2tf_u(As[(r + 8) * 36 + c + 4]);
            }
#pragma unroll
            for (int nt = 0; nt < 8; nt++) {
                int n = wn * 64 + nt * 8 + lg;
                bf[nt][0] = __float_as_uint(Bs[n * 36 + c]);
                bf[nt][1] = __float_as_uint(Bs[n * 36 + c + 4]);
            }
#pragma unroll
            for (int mt = 0; mt < 2; mt++)
#pragma unroll
                for (int nt = 0; nt < 8; nt++)
                    mma8(acc[mt][nt], ah[mt], bf[nt]);
        }
    }

    __syncthreads();
    float* partS = sm;
    float* partQ = sm + 256;

    float rs[4] = {0.f, 0.f, 0.f, 0.f}, rq[4] = {0.f, 0.f, 0.f, 0.f};
#pragma unroll
    for (int mt = 0; mt < 2; mt++) {
        int rl = wm * 32 + mt * 16 + lg;
#pragma unroll
        for (int nt = 0; nt < 8; nt++) {
            int col = wn * 64 + nt * 8 + (lt << 1);
            float2 bb = *(const float2*)&bias[col];
            float2 ra = *(const float2*)&res[(size_t)(bm + rl) * DD + col];
            float2 rb = *(const float2*)&res[(size_t)(bm + rl + 8) * DD + col];
            acc[mt][nt][0] += bb.x + ra.x;
            acc[mt][nt][1] += bb.y + ra.y;
            acc[mt][nt][2] += bb.x + rb.x;
            acc[mt][nt][3] += bb.y + rb.y;
            rs[mt * 2 + 0] += acc[mt][nt][0] + acc[mt][nt][1];
            rq[mt * 2 + 0] += acc[mt][nt][0] * acc[mt][nt][0] + acc[mt][nt][1] * acc[mt][nt][1];
            rs[mt * 2 + 1] += acc[mt][nt][2] + acc[mt][nt][3];
            rq[mt * 2 + 1] += acc[mt][nt][2] * acc[mt][nt][2] + acc[mt][nt][3] * acc[mt][nt][3];
        }
    }
#pragma unroll
    for (int j = 0; j < 4; j++) {
        rs[j] += __shfl_xor_sync(0xffffffffu, rs[j], 1);
        rs[j] += __shfl_xor_sync(0xffffffffu, rs[j], 2);
        rq[j] += __shfl_xor_sync(0xffffffffu, rq[j], 1);
        rq[j] += __shfl_xor_sync(0xffffffffu, rq[j], 2);
    }
    if (lt == 0) {
#pragma unroll
        for (int mt = 0; mt < 2; mt++)
#pragma unroll
            for (int i = 0; i < 2; i++) {
                int row = wm * 32 + mt * 16 + lg + i * 8;
                partS[wn * 64 + row] = rs[mt * 2 + i];
                partQ[wn * 64 + row] = rq[mt * 2 + i];
            }
    }
    __syncthreads();

#pragma unroll
    for (int mt = 0; mt < 2; mt++) {
        int rl = wm * 32 + mt * 16 + lg;
        float mu[2], inv[2];
#pragma unroll
        for (int i = 0; i < 2; i++) {
            int row = rl + i * 8;
            float S = partS[row] + partS[64 + row] + partS[128 + row] + partS[192 + row];
            float Q = partQ[row] + partQ[64 + row] + partQ[128 + row] + partQ[192 + row];
            mu[i] = S * (1.0f / DD);
            float var = Q * (1.0f / DD) - mu[i] * mu[i];
            inv[i] = rsqrtf(var + 1e-5f);
        }
#pragma unroll
        for (int nt = 0; nt < 8; nt++) {
            int col = wn * 64 + nt * 8 + (lt << 1);
            float2 wv = *(const float2*)&lnw[col];
            float2 bv = *(const float2*)&lnb[col];
            float y0 = (acc[mt][nt][0] - mu[0]) * inv[0] * wv.x + bv.x;
            float y1 = (acc[mt][nt][1] - mu[0]) * inv[0] * wv.y + bv.y;
            float y2 = (acc[mt][nt][2] - mu[1]) * inv[1] * wv.x + bv.x;
            float y3 = (acc[mt][nt][3] - mu[1]) * inv[1] * wv.y + bv.y;
            *(float2*)&Y[(size_t)(bm + rl) * DD + col] = make_float2(y0, y1);
            *(float2*)&Y[(size_t)(bm + rl + 8) * DD + col] = make_float2(y2, y3);
        }
    }
}

// ---------------- CSR build (once per launch) ----------------
__global__ void csr_zero_kernel() {
    int i = blockIdx.x * blockDim.x + threadIdx.x;
    if (i < NN) g_deg[i] = 0;
}

__global__ void csr_hist_kernel(const int* __restrict__ dst, int E, int Etot) {
    int e = blockIdx.x * blockDim.x + threadIdx.x;
    if (e >= Etot) return;
    int d = (e < E) ? dst[e] : (e - E);
    atomicAdd(&g_deg[d], 1);
}

__global__ void __launch_bounds__(1024) csr_scan_kernel() {
    __shared__ int wsum[32];
    int t = threadIdx.x;
    int lane = t & 31, w = t >> 5;
    int base = t * 8;
    int local[8];
    int s = 0;
#pragma unroll
    for (int j = 0; j < 8; j++) { local[j] = s; s += g_deg[base + j]; }
    int v = s;
#pragma unroll
    for (int off = 1; off < 32; off <<= 1) {
        int u = __shfl_up_sync(0xffffffffu, v, off);
        if (lane >= off) v += u;
    }
    if (lane == 31) wsum[w] = v;
    __syncthreads();
    if (w == 0) {
        int x = wsum[lane];
#pragma unroll
        for (int off = 1; off < 32; off <<= 1) {
            int u = __shfl_up_sync(0xffffffffu, x, off);
            if (lane >= off) x += u;
        }
        wsum[lane] = x;
    }
    __syncthreads();
    int prefix = v - s + ((w > 0) ? wsum[w - 1] : 0);
#pragma unroll
    for (int j = 0; j < 8; j++) {
        int o = prefix + local[j];
        g_off[base + j] = o;
        g_pos[base + j] = o;
    }
    if (t == 1023) g_off[NN] = wsum[31];
}

__global__ void csr_fill_kernel(const int* __restrict__ src, const int* __restrict__ dst,
                                int E, int Etot) {
    int e = blockIdx.x * blockDim.x + threadIdx.x;
    if (e >= Etot) return;
    int s, d;
    if (e < E) { s = src[e]; d = dst[e]; } else { s = d = e - E; }
    int p = atomicAdd(&g_pos[d], 1);
    g_esrc[p] = s;
    g_edst[p] = d;
}

// ---------------- fused GAT gather: inline edge softmax weights -------------------
// p = exp(leakyrelu(as[s,h] + ad[d,h])); out = (sum p*h[s]) / (sum p) + bias, relu
__global__ void __launch_bounds__(256) gat_gather_kernel(
    const float* __restrict__ hl, const float* __restrict__ as_,
    const float* __restrict__ ad_, const float* __restrict__ bias,
    float* __restrict__ out)
{
    const int d = blockIdx.x;
    const int h = threadIdx.x >> 5, lane = threadIdx.x & 31;
    const int beg = g_off[d], end = g_off[d + 1];
    const int hc = h * 32 + lane;
    const float adh = ad_[d * 8 + h];

    float acc0 = 0.f, acc1 = 0.f, acc2 = 0.f, acc3 = 0.f;
    float ss = 0.f;
    int i = beg;
    for (; i + 4 <= end; i += 4) {
        int s0 = g_esrc[i], s1 = g_esrc[i + 1], s2 = g_esrc[i + 2], s3 = g_esrc[i + 3];
        float a0 = as_[s0 * 8 + h] + adh;
        float a1 = as_[s1 * 8 + h] + adh;
        float a2 = as_[s2 * 8 + h] + adh;
        float a3 = as_[s3 * 8 + h] + adh;
        a0 = (a0 > 0.f) ? a0 : 0.2f * a0;
        a1 = (a1 > 0.f) ? a1 : 0.2f * a1;
        a2 = (a2 > 0.f) ? a2 : 0.2f * a2;
        a3 = (a3 > 0.f) ? a3 : 0.2f * a3;
        float p0 = __expf(a0), p1 = __expf(a1), p2 = __expf(a2), p3 = __expf(a3);
        float v0 = hl[(size_t)s0 * DD + hc];
        float v1 = hl[(size_t)s1 * DD + hc];
        float v2 = hl[(size_t)s2 * DD + hc];
        float v3 = hl[(size_t)s3 * DD + hc];
        ss += (p0 + p1) + (p2 + p3);
        acc0 = fmaf(p0, v0, acc0);
        acc1 = fmaf(p1, v1, acc1);
        acc2 = fmaf(p2, v2, acc2);
        acc3 = fmaf(p3, v3, acc3);
    }
    for (; i < end; i++) {
        int s0 = g_esrc[i];
        float a0 = as_[s0 * 8 + h] + adh;
        a0 = (a0 > 0.f) ? a0 : 0.2f * a0;
        float p0 = __expf(a0);
        ss += p0;
        acc0 = fmaf(p0, hl[(size_t)s0 * DD + hc], acc0);
    }
    float acc = (acc0 + acc1) + (acc2 + acc3);
    out[(size_t)d * DD + hc] = fmaxf(acc / ss + bias[hc], 0.f);
}

// ---------------- MMA flash-attention: 128 queries / CTA, no max-shift -----------
__global__ void __launch_bounds__(128) attn_mma_kernel(const float* __restrict__ qkv,
                                                       float* __restrict__ out)
{
    extern __shared__ __align__(16) float asm_[];
    float (*Qs)[36] = (float(*)[36])asm_;
    float (*Ks)[36] = (float(*)[36])(asm_ + 128 * 36);
    float (*Vt)[68] = (float(*)[68])(asm_ + 128 * 36 + 64 * 36);
    float (*Ps)[68] = (float(*)[68])(asm_ + 128 * 36 + 64 * 36 + 32 * 68);

    const int bh = blockIdx.x, b = bh >> 3, h = bh & 7;
    const int qt = blockIdx.y;
    const int tid = threadIdx.x;
    const int warp = tid >> 5, lane = tid & 31;
    const int lg = lane >> 2, lt = lane & 3;
    const float* base = qkv + (size_t)b * LL * 768;
    const float scale = 0.17677669529663687f;

#pragma unroll
    for (int i = 0; i < 8; i++) {
        int idx = tid + i * 128;
        int row = idx >> 3, c4 = (idx & 7) << 2;
        float4 v = *(const float4*)(base + (size_t)(qt * 128 + row) * 768 + h * 32 + c4);
        Qs[row][c4 + 0] = f2tf_f(v.x * scale);
        Qs[row][c4 + 1] = f2tf_f(v.y * scale);
        Qs[row][c4 + 2] = f2tf_f(v.z * scale);
        Qs[row][c4 + 3] = f2tf_f(v.w * scale);
    }

    float l[4] = {0.f, 0.f, 0.f, 0.f};
    float o[2][4][4];
#pragma unroll
    for (int mg = 0; mg < 2; mg++)
#pragma unroll
        for (int nt = 0; nt < 4; nt++)
#pragma unroll
            for (int r = 0; r < 4; r++) o[mg][nt][r] = 0.f;

    for (int kt = 0; kt < 16; kt++) {
        __syncthreads();
#pragma unroll
        for (int i = 0; i < 4; i++) {
            int idx = tid + i * 128;
            int row = idx >> 3, c4 = (idx & 7) << 2;
            const float* kp = base + (size_t)(kt * 64 + row) * 768 + 256 + h * 32 + c4;
            float4 kv = *(const float4*)kp;
            Ks[row][c4 + 0] = f2tf_f(kv.x);
            Ks[row][c4 + 1] = f2tf_f(kv.y);
            Ks[row][c4 + 2] = f2tf_f(kv.z);
            Ks[row][c4 + 3] = f2tf_f(kv.w);
            float4 vv = *(const float4*)(kp + 256);
            Vt[c4 + 0][row] = f2tf_f(vv.x);
            Vt[c4 + 1][row] = f2tf_f(vv.y);
            Vt[c4 + 2][row] = f2tf_f(vv.z);
            Vt[c4 + 3][row] = f2tf_f(vv.w);
        }
        __syncthreads();

#pragma unroll
        for (int mg = 0; mg < 2; mg++) {
            const int r0 = warp * 32 + mg * 16 + lg;
            float s[8][4];
#pragma unroll
            for (int nt = 0; nt < 8; nt++)
#pragma unroll
                for (int r = 0; r < 4; r++) s[nt][r] = 0.f;
#pragma unroll
            for (int kk = 0; kk < 4; kk++) {
                const int c = kk * 8 + lt;
                unsigned a[4];
                a[0] = __float_as_uint(Qs[r0][c]);
                a[1] = __float_as_uint(Qs[r0 + 8][c]);
                a[2] = __float_as_uint(Qs[r0][c + 4]);
                a[3] = __float_as_uint(Qs[r0 + 8][c + 4]);
#pragma unroll
                for (int nt = 0; nt < 8; nt++) {
                    unsigned bb[2];
                    bb[0] = __float_as_uint(Ks[nt * 8 + lg][c]);
                    bb[1] = __float_as_uint(Ks[nt * 8 + lg][c + 4]);
                    mma8(s[nt], a, bb);
                }
            }
            float ps0 = 0.f, ps1 = 0.f;
#pragma unroll
            for (int nt = 0; nt < 8; nt++) {
                float p0 = __expf(s[nt][0]);
                float p1 = __expf(s[nt][1]);
                float p2 = __expf(s[nt][2]);
                float p3 = __expf(s[nt][3]);
                ps0 += p0 + p1;
                ps1 += p2 + p3;
                int col = nt * 8 + (lt << 1);
                Ps[r0][col]     = f2tf_f(p0);
                Ps[r0][col + 1] = f2tf_f(p1);
                Ps[r0 + 8][col]     = f2tf_f(p2);
                Ps[r0 + 8][col + 1] = f2tf_f(p3);
            }
            l[mg * 2 + 0] += ps0;
            l[mg * 2 + 1] += ps1;
        }
        __syncwarp();

#pragma unroll
        for (int mg = 0; mg < 2; mg++) {
            const int r0 = warp * 32 + mg * 16 + lg;
#pragma unroll
            for (int kk = 0; kk < 8; kk++) {
                const int c = kk * 8 + lt;
                unsigned a[4];
                a[0] = __float_as_uint(Ps[r0][c]);
                a[1] = __float_as_uint(Ps[r0 + 8][c]);
                a[2] = __float_as_uint(Ps[r0][c + 4]);
                a[3] = __float_as_uint(Ps[r0 + 8][c + 4]);
#pragma unroll
                for (int nt = 0; nt < 4; nt++) {
                    unsigned bb[2];
                    bb[0] = __float_as_uint(Vt[nt * 8 + lg][c]);
                    bb[1] = __float_as_uint(Vt[nt * 8 + lg][c + 4]);
                    mma8(o[mg][nt], a, bb);
                }
            }
        }
    }

#pragma unroll
    for (int j = 0; j < 4; j++) {
        l[j] += __shfl_xor_sync(0xffffffffu, l[j], 1);
        l[j] += __shfl_xor_sync(0xffffffffu, l[j], 2);
    }

#pragma unroll
    for (int mg = 0; mg < 2; mg++) {
        float inv0 = 1.0f / l[mg * 2 + 0];
        float inv1 = 1.0f / l[mg * 2 + 1];
        int q0 = qt * 128 + warp * 32 + mg * 16 + lg;
        float* op = out + (size_t)(b * LL + q0) * DD + h * 32;
#pragma unroll
        for (int nt = 0; nt < 4; nt++) {
            int col = nt * 8 + (lt << 1);
            *(float2*)(op + col) = make_float2(o[mg][nt][0] * inv0, o[mg][nt][1] * inv0);
            *(float2*)(op + 8 * DD + col) = make_float2(o[mg][nt][2] * inv1, o[mg][nt][3] * inv1);
        }
    }
}

// ---------------- final prediction ----------------
__global__ void __launch_bounds__(256) pred_kernel(
    const float* __restrict__ x, const float* __restrict__ pw,
    const float* __restrict__ pb, float* __restrict__ out)
{
    int n = blockIdx.x * 8 + (threadIdx.x >> 5);
    int lane = threadIdx.x & 31;
    const float* xr = x + (size_t)n * DD;
    float xv[8];
#pragma unroll
    for (int k = 0; k < 8; k++) xv[k] = xr[lane + 32 * k];
    float a0 = 0.f, a1 = 0.f, a2 = 0.f;
#pragma unroll
    for (int k = 0; k < 8; k++) {
        int c = lane + 32 * k;
        a0 += xv[k] * pw[0 * DD + c];
        a1 += xv[k] * pw[1 * DD + c];
        a2 += xv[k] * pw[2 * DD + c];
    }
#pragma unroll
    for (int o = 16; o; o >>= 1) {
        a0 += __shfl_xor_sync(0xffffffffu, a0, o);
        a1 += __shfl_xor_sync(0xffffffffu, a1, o);
        a2 += __shfl_xor_sync(0xffffffffu, a2, o);
    }
    if (lane == 0) {
        out[n * 3 + 0] = a0 + pb[0];
        out[n * 3 + 1] = a1 + pb[1];
        out[n * 3 + 2] = a2 + pb[2];
    }
}

// ---------------- host orchestration ----------------
extern "C" void kernel_launch(void* const* d_in, const int* in_sizes, int n_in,
                              void* d_out, int out_size)
{
    const float* x        = (const float*)d_in[0];
    const int*   ei       = (const int*)  d_in[1];
    const float* gat_W0   = (const float*)d_in[3];
    const float* gat_W12  = (const float*)d_in[4];
    const float* att_src  = (const float*)d_in[5];
    const float* att_dst  = (const float*)d_in[6];
    const float* gat_bias = (const float*)d_in[7];
    const float* qkv_w    = (const float*)d_in[8];
    const float* qkv_b    = (const float*)d_in[9];
    const float* out_w    = (const float*)d_in[10];
    const float* out_b    = (const float*)d_in[11];
    const float* ln1_w    = (const float*)d_in[12];
    const float* ln1_b    = (const float*)d_in[13];
    const float* ln2_w    = (const float*)d_in[14];
    const float* ln2_b    = (const float*)d_in[15];
    const float* ff1_w    = (const float*)d_in[16];
    const float* ff1_b    = (const float*)d_in[17];
    const float* ff2_w    = (const float*)d_in[18];
    const float* ff2_b    = (const float*)d_in[19];
    const float* pred_w   = (const float*)d_in[20];
    const float* pred_b   = (const float*)d_in[21];

    const int E = in_sizes[1] / 2;
    const int Etot = E + NN;
    const int* src = ei;
    const int* dst = ei + E;

    float *hl, *h0, *h1, *as_, *ad_, *qkv, *attn, *ff, *wr;
    cudaGetSymbolAddress((void**)&hl,   g_hl);
    cudaGetSymbolAddress((void**)&h0,   g_h0);
    cudaGetSymbolAddress((void**)&h1,   g_h1);
    cudaGetSymbolAddress((void**)&as_,  g_as);
    cudaGetSymbolAddress((void**)&ad_,  g_ad);
    cudaGetSymbolAddress((void**)&qkv,  g_qkv);
    cudaGetSymbolAddress((void**)&attn, g_attn);
    cudaGetSymbolAddress((void**)&ff,   g_ff);
    cudaGetSymbolAddress((void**)&wr,   g_wr);

    float* W0r  = wr;
    float* W12r = W0r  + W0_N;
    float* qwr  = W12r + W12_N;
    float* owr  = qwr  + QW_N;
    float* f1r  = owr  + OW_N;
    float* f2r  = f1r  + F1_N;

    cudaFuncSetAttribute(tgemm_kernel<1>, cudaFuncAttributeMaxDynamicSharedMemorySize, TG_SMEM2);
    cudaFuncSetAttribute(tgemm_kernel<2>, cudaFuncAttributeMaxDynamicSharedMemorySize, TG_SMEM2);
    cudaFuncSetAttribute(tgemm_kernel<3>, cudaFuncAttributeMaxDynamicSharedMemorySize, TG_SMEM2);
    cudaFuncSetAttribute(tgemm_ln_kernel, cudaFuncAttributeMaxDynamicSharedMemorySize, TL_SMEM3);
    cudaFuncSetAttribute(attn_mma_kernel, cudaFuncAttributeMaxDynamicSharedMemorySize, AT_SMEM);

    // pre-round all weights to tf32 (rna) in one launch
    round_all_kernel<<<(WR_N / 4 + 255) / 256, 256>>>(gat_W0, gat_W12, qkv_w, out_w,
                                                      ff1_w, ff2_w, wr);

    const int eb = (Etot + 255) / 256;

    // CSR build (once)
    csr_zero_kernel<<<(NN + 255) / 256, 256>>>();
    csr_hist_kernel<<<eb, 256>>>(dst, E, Etot);
    csr_scan_kernel<<<1, 1024>>>();
    csr_fill_kernel<<<eb, 256>>>(src, dst, E, Etot);

    auto gat_layer = [&](const float* in, int Din, const float* W,
                         const float* atts, const float* attd, const float* bias,
                         float* outp) {
        tgemm_kernel<3><<<dim3(DD / 128, NN / 128), 256, TG_SMEM2>>>(
            in, W, nullptr, hl, NN, DD, Din, atts, attd, as_, ad_);
        gat_gather_kernel<<<NN, 256>>>(hl, as_, ad_, bias, outp);
    };

    gat_layer(x,  INC, W0r,             att_src,           att_dst,           gat_bias,          h0);
    gat_layer(h0, DD,  W12r,            att_src + HH * CC, att_dst + HH * CC, gat_bias + DD,     h1);
    gat_layer(h1, DD,  W12r + DD * DD,  att_src + 2*HH*CC, att_dst + 2*HH*CC, gat_bias + 2 * DD, h0);

    for (int l = 0; l < 2; l++) {
        const float* qw  = qwr + (size_t)l * 3 * DD * DD;
        const float* qb  = qkv_b + l * 3 * DD;
        const float* ow  = owr + (size_t)l * DD * DD;
        const float* ob  = out_b + l * DD;
        const float* l1w = ln1_w + l * DD, * l1b = ln1_b + l * DD;
        const float* l2w = ln2_w + l * DD, * l2b = ln2_b + l * DD;
        const float* f1w = f1r + (size_t)l * DFF * DD;
        const float* f1b = ff1_b + l * DFF;
        const float* f2w = f2r + (size_t)l * DD * DFF;
        const float* f2b = ff2_b + l * DD;

        tgemm_kernel<1><<<dim3(3 * DD / 128, NN / 128), 256, TG_SMEM2>>>(
            h0, qw, qb, qkv, NN, 3 * DD, DD, nullptr, nullptr, nullptr, nullptr);
        attn_mma_kernel<<<dim3(BB * HH, LL / 128), 128, AT_SMEM>>>(qkv, attn);
        tgemm_ln_kernel<<<dim3(1, NN / 64), 256, TL_SMEM3>>>(attn, ow, ob, h0, l1w, l1b, h1, NN, DD);
        tgemm_kernel<2><<<dim3(DFF / 128, NN / 128), 256, TG_SMEM2>>>(
            h1, f1w, f1b, ff, NN, DFF, DD, nullptr, nullptr, nullptr, nullptr);
        tgemm_ln_kernel<<<dim3(1, NN / 64), 256, TL_SMEM3>>>(ff, f2w, f2b, h1, l2w, l2b, h0, NN, DFF);
    }

    pred_kernel<<<NN / 8, 256>>>(h0, pred_w, pred_b, (float*)d_out);
}

// round 16
// speedup vs baseline: 1.0348x; 1.0348x over previous
#include <cuda_runtime.h>
#include <math.h>
#include <stdint.h>

#define NN   8192
#define BB   8
#define LL   1024
#define INC  64
#define HH   8
#define CC   32
#define DD   256
#define DFF  2048
#define EMAX 262144
#define ETOTMAX (EMAX + NN)

#define TG_STG   (256 * 36)
#define TG_SMEM2 (2 * TG_STG * 4)        // 73728 B -> 2 CTAs/SM
#define TL_STG   (320 * 36)
#define TL_SMEM3 (3 * TL_STG * 4)

// attention smem (dynamic): Qs 128x36 + Ks 64x36 + Vt 32x68 + Ps 128x68
#define AT_SMEM ((128 * 36 + 64 * 36 + 32 * 68 + 128 * 68) * 4)

// pre-rounded weight scratch sizes (floats)
#define W0_N   (DD * INC)
#define W12_N  (2 * DD * DD)
#define QW_N   (2 * 3 * DD * DD)
#define OW_N   (2 * DD * DD)
#define F1_N   (2 * DFF * DD)
#define F2_N   (2 * DD * DFF)
#define WR_N   (W0_N + W12_N + QW_N + OW_N + F1_N + F2_N)

// ---------------- scratch (device globals; no runtime allocation) ----------------
__device__ float g_hl  [NN * DD];
__device__ float g_h0  [NN * DD];
__device__ float g_h1  [NN * DD];
__device__ float g_as  [NN * HH];
__device__ float g_ad  [NN * HH];
__device__ float g_pe  [ETOTMAX * HH];
__device__ float g_qkv [NN * 3 * DD];
__device__ float g_attn[NN * DD];
__device__ float g_ff  [NN * DFF];
__device__ float g_wr  [WR_N];
// CSR (built once per launch)
__device__ int   g_deg [NN];
__device__ int   g_off [NN + 1];
__device__ int   g_pos [NN];
__device__ int   g_esrc[ETOTMAX];
__device__ int   g_edst[ETOTMAX];

// ---------------- helpers ----------------
__device__ __forceinline__ float f2tf_f(float f) {
    unsigned u;
    asm("cvt.rna.tf32.f32 %0, %1;" : "=r"(u) : "f"(f));
    return __uint_as_float(u);
}

__device__ __forceinline__ unsigned f2tf_u(float f) {
    unsigned u;
    asm("cvt.rna.tf32.f32 %0, %1;" : "=r"(u) : "f"(f));
    return u;
}

__device__ __forceinline__ void mma8(float* d, const unsigned* a, const unsigned* b) {
    asm volatile(
        "mma.sync.aligned.m16n8k8.row.col.f32.tf32.tf32.f32 "
        "{%0,%1,%2,%3},{%4,%5,%6,%7},{%8,%9},{%0,%1,%2,%3};"
        : "+f"(d[0]), "+f"(d[1]), "+f"(d[2]), "+f"(d[3])
        : "r"(a[0]), "r"(a[1]), "r"(a[2]), "r"(a[3]), "r"(b[0]), "r"(b[1]));
}

#define CP16(dst_u32, src_ptr) \
    asm volatile("cp.async.cg.shared.global [%0], [%1], 16;\n" :: "r"(dst_u32), "l"(src_ptr))
#define CP_COMMIT() asm volatile("cp.async.commit_group;\n" ::)
#define CP_WAIT1()  asm volatile("cp.async.wait_group 1;\n" ::)

// ---------------- merged tf32 pre-round (once per launch, all weights) ----------
__global__ void round_all_kernel(const float* __restrict__ s0, const float* __restrict__ s1,
                                 const float* __restrict__ s2, const float* __restrict__ s3,
                                 const float* __restrict__ s4, const float* __restrict__ s5,
                                 float* __restrict__ dst)
{
    int i = blockIdx.x * blockDim.x + threadIdx.x;   // float4 index
    if (i >= WR_N / 4) return;
    int f = i * 4;
    const float* src;
    int off;
    if (f < W0_N)                                  { src = s0; off = f; }
    else if (f < W0_N + W12_N)                     { src = s1; off = f - W0_N; }
    else if (f < W0_N + W12_N + QW_N)              { src = s2; off = f - (W0_N + W12_N); }
    else if (f < W0_N + W12_N + QW_N + OW_N)       { src = s3; off = f - (W0_N + W12_N + QW_N); }
    else if (f < W0_N + W12_N + QW_N + OW_N + F1_N){ src = s4; off = f - (W0_N + W12_N + QW_N + OW_N); }
    else                                           { src = s5; off = f - (W0_N + W12_N + QW_N + OW_N + F1_N); }
    float4 v = *(const float4*)(src + off);
    v.x = f2tf_f(v.x); v.y = f2tf_f(v.y);
    v.z = f2tf_f(v.z); v.w = f2tf_f(v.w);
    ((float4*)dst)[i] = v;
}

// ---------------- cp.async 2-stage tensor-core GEMM (2 CTAs/SM) -------------------
// BIASMODE: 0 none, 1 bias, 2 bias+relu, 3 GAT (no bias/relu; fused coef dot)
template<int BIASMODE>
__global__ void __launch_bounds__(256, 2) tgemm_kernel(
    const float* __restrict__ A, const float* __restrict__ W,
    const float* __restrict__ bias, float* __restrict__ C,
    int M, int Nn, int K,
    const float* __restrict__ atts, const float* __restrict__ attd,
    float* __restrict__ asv, float* __restrict__ adv)
{
    extern __shared__ __align__(16) float sm[];
    unsigned sbase = (unsigned)__cvta_generic_to_shared(sm);

    const int bm = blockIdx.y * 128;
    const int bn = blockIdx.x * 128;
    const int tid = threadIdx.x;
    const int warp = tid >> 5, lane = tid & 31;
    const int wm = warp & 3, wn = warp >> 2;
    const int lg = lane >> 2, lt = lane & 3;

    int lrow[4], lc4[4];
#pragma unroll
    for (int i = 0; i < 4; i++) {
        int f4 = tid + i * 256;
        lrow[i] = f4 >> 3;
        lc4[i] = (f4 & 7) << 2;
    }

    float acc[2][8][4];
#pragma unroll
    for (int mt = 0; mt < 2; mt++)
#pragma unroll
        for (int nt = 0; nt < 8; nt++)
#pragma unroll
            for (int r = 0; r < 4; r++) acc[mt][nt][r] = 0.0f;

    const int nk = K >> 5;
    auto issue = [&](int t) {
        if (t < nk) {
            int k0 = t << 5;
            unsigned so = sbase + (unsigned)((t & 1) * TG_STG) * 4u;
#pragma unroll
            for (int i = 0; i < 4; i++) {
                const float* gA = A + (size_t)(bm + lrow[i]) * K + k0 + lc4[i];
                const float* gB = W + (size_t)(bn + lrow[i]) * K + k0 + lc4[i];
                CP16(so + (unsigned)(lrow[i] * 36 + lc4[i]) * 4u, gA);
                CP16(so + (unsigned)((128 * 36) + lrow[i] * 36 + lc4[i]) * 4u, gB);
            }
        }
        CP_COMMIT();
    };

    issue(0);
    for (int t = 0; t < nk; t++) {
        issue(t + 1);
        CP_WAIT1();
        __syncthreads();
        const float* As = sm + (t & 1) * TG_STG;
        const float* Bs = As + 128 * 36;
#pragma unroll
        for (int kk = 0; kk < 32; kk += 8) {
            unsigned ah[2][4], bf[8][2];
            const int c = kk + lt;
#pragma unroll
            for (int mt = 0; mt < 2; mt++) {
                int r = wm * 32 + mt * 16 + lg;
                ah[mt][0] = f2tf_u(As[r * 36 + c]);
                ah[mt][1] = f2tf_u(As[(r + 8) * 36 + c]);
                ah[mt][2] = f2tf_u(As[r * 36 + c + 4]);
                ah[mt][3] = f2tf_u(As[(r + 8) * 36 + c + 4]);
            }
#pragma unroll
            for (int nt = 0; nt < 8; nt++) {
                int n = wn * 64 + nt * 8 + lg;
                bf[nt][0] = __float_as_uint(Bs[n * 36 + c]);
                bf[nt][1] = __float_as_uint(Bs[n * 36 + c + 4]);
            }
#pragma unroll
            for (int mt = 0; mt < 2; mt++)
#pragma unroll
                for (int nt = 0; nt < 8; nt++)
                    mma8(acc[mt][nt], ah[mt], bf[nt]);
        }
        __syncthreads();
    }

    // fused GAT coef partials: [mt][rowhalf][head-in-warp(2)]
    float aS[2][2][2], aD[2][2][2];
    if (BIASMODE == 3) {
#pragma unroll
        for (int a = 0; a < 2; a++)
#pragma unroll
            for (int b2 = 0; b2 < 2; b2++)
#pragma unroll
                for (int c2 = 0; c2 < 2; c2++) { aS[a][b2][c2] = 0.f; aD[a][b2][c2] = 0.f; }
    }

#pragma unroll
    for (int mt = 0; mt < 2; mt++) {
#pragma unroll
        for (int nt = 0; nt < 8; nt++) {
            int row = bm + wm * 32 + mt * 16 + lg;
            int col = bn + wn * 64 + nt * 8 + (lt << 1);
            float b0 = 0.f, b1 = 0.f;
            if (BIASMODE == 1 || BIASMODE == 2) { b0 = bias[col]; b1 = bias[col + 1]; }
            float v0 = acc[mt][nt][0] + b0, v1 = acc[mt][nt][1] + b1;
            float v2 = acc[mt][nt][2] + b0, v3 = acc[mt][nt][3] + b1;
            if (BIASMODE == 2) {
                v0 = fmaxf(v0, 0.f); v1 = fmaxf(v1, 0.f);
                v2 = fmaxf(v2, 0.f); v3 = fmaxf(v3, 0.f);
            }
            if (BIASMODE == 3) {
                int hs = nt >> 2;
                float2 ts = *(const float2*)&atts[col];
                float2 td = *(const float2*)&attd[col];
                aS[mt][0][hs] += v0 * ts.x + v1 * ts.y;
                aS[mt][1][hs] += v2 * ts.x + v3 * ts.y;
                aD[mt][0][hs] += v0 * td.x + v1 * td.y;
                aD[mt][1][hs] += v2 * td.x + v3 * td.y;
            }
            *(float2*)&C[(size_t)row * Nn + col] = make_float2(v0, v1);
            *(float2*)&C[(size_t)(row + 8) * Nn + col] = make_float2(v2, v3);
        }
    }

    if (BIASMODE == 3) {
#pragma unroll
        for (int mt = 0; mt < 2; mt++)
#pragma unroll
            for (int hf = 0; hf < 2; hf++)
#pragma unroll
                for (int hs = 0; hs < 2; hs++) {
                    float s = aS[mt][hf][hs], d = aD[mt][hf][hs];
                    s += __shfl_xor_sync(0xffffffffu, s, 1);
                    s += __shfl_xor_sync(0xffffffffu, s, 2);
                    d += __shfl_xor_sync(0xffffffffu, d, 1);
                    d += __shfl_xor_sync(0xffffffffu, d, 2);
                    aS[mt][hf][hs] = s; aD[mt][hf][hs] = d;
                }
        if (lt == 0) {
            int headbase = (bn + wn * 64) >> 5;
#pragma unroll
            for (int mt = 0; mt < 2; mt++)
#pragma unroll
                for (int hf = 0; hf < 2; hf++) {
                    int row = bm + wm * 32 + mt * 16 + lg + hf * 8;
#pragma unroll
                    for (int hs = 0; hs < 2; hs++) {
                        asv[row * 8 + headbase + hs] = aS[mt][hf][hs];
                        adv[row * 8 + headbase + hs] = aD[mt][hf][hs];
                    }
                }
        }
    }
}

// ---------------- GEMM + residual + LayerNorm fused (BM=64, BN=256, 3-stage) ----
// PRED=1: additionally compute final prediction out[n,0..2] = LN(y) . pred_w + pred_b
//         and skip storing Y (pred is its only consumer).
template<int PRED>
__global__ void __launch_bounds__(256) tgemm_ln_kernel(
    const float* __restrict__ A, const float* __restrict__ W,
    const float* __restrict__ bias, const float* __restrict__ res,
    const float* __restrict__ lnw, const float* __restrict__ lnb,
    float* __restrict__ Y, int M, int K,
    const float* __restrict__ pw, const float* __restrict__ pb,
    float* __restrict__ pout)
{
    extern __shared__ __align__(16) float sm[];
    unsigned sbase = (unsigned)__cvta_generic_to_shared(sm);

    const int bm = blockIdx.y * 64;
    const int tid = threadIdx.x;
    const int warp = tid >> 5, lane = tid & 31;
    const int wm = warp & 1, wn = warp >> 1;
    const int lg = lane >> 2, lt = lane & 3;

    int arow[2], ac4[2], brow[8], bc4[8];
#pragma unroll
    for (int i = 0; i < 2; i++) {
        int f4 = tid + i * 256;
        arow[i] = f4 >> 3; ac4[i] = (f4 & 7) << 2;
    }
#pragma unroll
    for (int i = 0; i < 8; i++) {
        int f4 = tid + i * 256;
        brow[i] = f4 >> 3; bc4[i] = (f4 & 7) << 2;
    }

    float acc[2][8][4];
#pragma unroll
    for (int mt = 0; mt < 2; mt++)
#pragma unroll
        for (int nt = 0; nt < 8; nt++)
#pragma unroll
            for (int r = 0; r < 4; r++) acc[mt][nt][r] = 0.0f;

    const int nk = K >> 5;
    auto issue = [&](int t) {
        if (t < nk) {
            int k0 = t << 5;
            unsigned so = sbase + (unsigned)((t % 3) * TL_STG) * 4u;
#pragma unroll
            for (int i = 0; i < 2; i++) {
                const float* gA = A + (size_t)(bm + arow[i]) * K + k0 + ac4[i];
                CP16(so + (unsigned)(arow[i] * 36 + ac4[i]) * 4u, gA);
            }
#pragma unroll
            for (int i = 0; i < 8; i++) {
                const float* gB = W + (size_t)brow[i] * K + k0 + bc4[i];
                CP16(so + (unsigned)((64 * 36) + brow[i] * 36 + bc4[i]) * 4u, gB);
            }
        }
        CP_COMMIT();
    };

    issue(0); issue(1);
    for (int t = 0; t < nk; t++) {
        CP_WAIT1();
        __syncthreads();
        issue(t + 2);
        const float* As = sm + (t % 3) * TL_STG;
        const float* Bs = As + 64 * 36;
#pragma unroll
        for (int kk = 0; kk < 32; kk += 8) {
            unsigned ah[2][4], bf[8][2];
            const int c = kk + lt;
#pragma unroll
            for (int mt = 0; mt < 2; mt++) {
                int r = wm * 32 + mt * 16 + lg;
                ah[mt][0] = f2tf_u(As[r * 36 + c]);
                ah[mt][1] = f2tf_u(As[(r + 8) * 36 + c]);
                ah[mt][2] = f2tf_u(As[r * 36 + c + 4]);
                ah[mt][3] = f2tf_u(As[(r + 8) * 36 + c + 4]);
            }
#pragma unroll
            for (int nt = 0; nt < 8; nt++) {
                int n = wn * 64 + nt * 8 + lg;
                bf[nt][0] = __float_as_uint(Bs[n * 36 + c]);
                bf[nt][1] = __float_as_uint(Bs[n * 36 + c + 4]);
            }
#pragma unroll
            for (int mt = 0; mt < 2; mt++)
#pragma unroll
                for (int nt = 0; nt < 8; nt++)
                    mma8(acc[mt][nt], ah[mt], bf[nt]);
        }
    }

    __syncthreads();
    float* partS = sm;                 // [4][64]
    float* partQ = sm + 256;           // [4][64]
    float* pwsm  = sm + 512;           // [3][256] (PRED only)
    float* partP = sm + 512 + 768;     // [4][64][3] (PRED only)

    if (PRED) {
        for (int i = tid; i < 3 * DD; i += 256) pwsm[i] = pw[i];
    }

    float rs[4] = {0.f, 0.f, 0.f, 0.f}, rq[4] = {0.f, 0.f, 0.f, 0.f};
#pragma unroll
    for (int mt = 0; mt < 2; mt++) {
        int rl = wm * 32 + mt * 16 + lg;
#pragma unroll
        for (int nt = 0; nt < 8; nt++) {
            int col = wn * 64 + nt * 8 + (lt << 1);
            float2 bb = *(const float2*)&bias[col];
            float2 ra = *(const float2*)&res[(size_t)(bm + rl) * DD + col];
            float2 rb = *(const float2*)&res[(size_t)(bm + rl + 8) * DD + col];
            acc[mt][nt][0] += bb.x + ra.x;
            acc[mt][nt][1] += bb.y + ra.y;
            acc[mt][nt][2] += bb.x + rb.x;
            acc[mt][nt][3] += bb.y + rb.y;
            rs[mt * 2 + 0] += acc[mt][nt][0] + acc[mt][nt][1];
            rq[mt * 2 + 0] += acc[mt][nt][0] * acc[mt][nt][0] + acc[mt][nt][1] * acc[mt][nt][1];
            rs[mt * 2 + 1] += acc[mt][nt][2] + acc[mt][nt][3];
            rq[mt * 2 + 1] += acc[mt][nt][2] * acc[mt][nt][2] + acc[mt][nt][3] * acc[mt][nt][3];
        }
    }
#pragma unroll
    for (int j = 0; j < 4; j++) {
        rs[j] += __shfl_xor_sync(0xffffffffu, rs[j], 1);
        rs[j] += __shfl_xor_sync(0xffffffffu, rs[j], 2);
        rq[j] += __shfl_xor_sync(0xffffffffu, rq[j], 1);
        rq[j] += __shfl_xor_sync(0xffffffffu, rq[j], 2);
    }
    if (lt == 0) {
#pragma unroll
        for (int mt = 0; mt < 2; mt++)
#pragma unroll
            for (int i = 0; i < 2; i++) {
                int row = wm * 32 + mt * 16 + lg + i * 8;
                partS[wn * 64 + row] = rs[mt * 2 + i];
                partQ[wn * 64 + row] = rq[mt * 2 + i];
            }
    }
    __syncthreads();

    float pr[2][2][3];
    if (PRED) {
#pragma unroll
        for (int a = 0; a < 2; a++)
#pragma unroll
            for (int b2 = 0; b2 < 2; b2++)
#pragma unroll
                for (int j = 0; j < 3; j++) pr[a][b2][j] = 0.f;
    }

#pragma unroll
    for (int mt = 0; mt < 2; mt++) {
        int rl = wm * 32 + mt * 16 + lg;
        float mu[2], inv[2];
#pragma unroll
        for (int i = 0; i < 2; i++) {
            int row = rl + i * 8;
            float S = partS[row] + partS[64 + row] + partS[128 + row] + partS[192 + row];
            float Q = partQ[row] + partQ[64 + row] + partQ[128 + row] + partQ[192 + row];
            mu[i] = S * (1.0f / DD);
            float var = Q * (1.0f / DD) - mu[i] * mu[i];
            inv[i] = rsqrtf(var + 1e-5f);
        }
#pragma unroll
        for (int nt = 0; nt < 8; nt++) {
            int col = wn * 64 + nt * 8 + (lt << 1);
            float2 wv = *(const float2*)&lnw[col];
            float2 bv = *(const float2*)&lnb[col];
            float y0 = (acc[mt][nt][0] - mu[0]) * inv[0] * wv.x + bv.x;
            float y1 = (acc[mt][nt][1] - mu[0]) * inv[0] * wv.y + bv.y;
            float y2 = (acc[mt][nt][2] - mu[1]) * inv[1] * wv.x + bv.x;
            float y3 = (acc[mt][nt][3] - mu[1]) * inv[1] * wv.y + bv.y;
            if (PRED) {
#pragma unroll
                for (int j = 0; j < 3; j++) {
                    float w0 = pwsm[j * DD + col], w1 = pwsm[j * DD + col + 1];
                    pr[mt][0][j] += y0 * w0 + y1 * w1;
                    pr[mt][1][j] += y2 * w0 + y3 * w1;
                }
            } else {
                *(float2*)&Y[(size_t)(bm + rl) * DD + col] = make_float2(y0, y1);
                *(float2*)&Y[(size_t)(bm + rl + 8) * DD + col] = make_float2(y2, y3);
            }
        }
    }

    if (PRED) {
#pragma unroll
        for (int mt = 0; mt < 2; mt++)
#pragma unroll
            for (int hf = 0; hf < 2; hf++)
#pragma unroll
                for (int j = 0; j < 3; j++) {
                    float v = pr[mt][hf][j];
                    v += __shfl_xor_sync(0xffffffffu, v, 1);
                    v += __shfl_xor_sync(0xffffffffu, v, 2);
                    pr[mt][hf][j] = v;
                }
        if (lt == 0) {
#pragma unroll
            for (int mt = 0; mt < 2; mt++)
#pragma unroll
                for (int hf = 0; hf < 2; hf++) {
                    int row = wm * 32 + mt * 16 + lg + hf * 8;
#pragma unroll
                    for (int j = 0; j < 3; j++)
                        partP[(wn * 64 + row) * 3 + j] = pr[mt][hf][j];
                }
        }
        __syncthreads();
        if (tid < 64) {
#pragma unroll
            for (int j = 0; j < 3; j++) {
                float v = partP[(0 * 64 + tid) * 3 + j] + partP[(1 * 64 + tid) * 3 + j]
                        + partP[(2 * 64 + tid) * 3 + j] + partP[(3 * 64 + tid) * 3 + j];
                pout[(size_t)(bm + tid) * 3 + j] = v + pb[j];
            }
        }
    }
}

// ---------------- CSR build (once per launch) ----------------
__global__ void csr_zero_kernel() {
    int i = blockIdx.x * blockDim.x + threadIdx.x;
    if (i < NN) g_deg[i] = 0;
}

__global__ void csr_hist_kernel(const int* __restrict__ dst, int E, int Etot) {
    int e = blockIdx.x * blockDim.x + threadIdx.x;
    if (e >= Etot) return;
    int d = (e < E) ? dst[e] : (e - E);
    atomicAdd(&g_deg[d], 1);
}

__global__ void __launch_bounds__(1024) csr_scan_kernel() {
    __shared__ int wsum[32];
    int t = threadIdx.x;
    int lane = t & 31, w = t >> 5;
    int base = t * 8;
    int local[8];
    int s = 0;
#pragma unroll
    for (int j = 0; j < 8; j++) { local[j] = s; s += g_deg[base + j]; }
    int v = s;
#pragma unroll
    for (int off = 1; off < 32; off <<= 1) {
        int u = __shfl_up_sync(0xffffffffu, v, off);
        if (lane >= off) v += u;
    }
    if (lane == 31) wsum[w] = v;
    __syncthreads();
    if (w == 0) {
        int x = wsum[lane];
#pragma unroll
        for (int off = 1; off < 32; off <<= 1) {
            int u = __shfl_up_sync(0xffffffffu, x, off);
            if (lane >= off) x += u;
        }
        wsum[lane] = x;
    }
    __syncthreads();
    int prefix = v - s + ((w > 0) ? wsum[w - 1] : 0);
#pragma unroll
    for (int j = 0; j < 8; j++) {
        int o = prefix + local[j];
        g_off[base + j] = o;
        g_pos[base + j] = o;
    }
    if (t == 1023) g_off[NN] = wsum[31];
}

__global__ void csr_fill_kernel(const int* __restrict__ src, const int* __restrict__ dst,
                                int E, int Etot) {
    int e = blockIdx.x * blockDim.x + threadIdx.x;
    if (e >= Etot) return;
    int s, d;
    if (e < E) { s = src[e]; d = dst[e]; } else { s = d = e - E; }
    int p = atomicAdd(&g_pos[d], 1);
    g_esrc[p] = s;
    g_edst[p] = d;
}

// ---------------- GAT edge/gather kernels (R14-proven) ----------------
__global__ void gat_edge_p_kernel(int Etot,
                                  const float* __restrict__ as_,
                                  const float* __restrict__ ad_,
                                  float* __restrict__ pe)
{
    int i = blockIdx.x * blockDim.x + threadIdx.x;
    if (i >= Etot) return;
    int s = g_esrc[i], d = g_edst[i];
    float4 s0 = *(const float4*)&as_[s * 8];
    float4 s1 = *(const float4*)&as_[s * 8 + 4];
    float4 d0 = *(const float4*)&ad_[d * 8];
    float4 d1 = *(const float4*)&ad_[d * 8 + 4];
    float a[8] = {s0.x + d0.x, s0.y + d0.y, s0.z + d0.z, s0.w + d0.w,
                  s1.x + d1.x, s1.y + d1.y, s1.z + d1.z, s1.w + d1.w};
#pragma unroll
    for (int h = 0; h < 8; h++) {
        float t = a[h];
        t = (t > 0.f) ? t : 0.2f * t;
        a[h] = __expf(t);
    }
    *(float4*)&pe[(size_t)i * 8]     = make_float4(a[0], a[1], a[2], a[3]);
    *(float4*)&pe[(size_t)i * 8 + 4] = make_float4(a[4], a[5], a[6], a[7]);
}

__global__ void __launch_bounds__(256) gat_gather_kernel(
    const float* __restrict__ hl, const float* __restrict__ pe,
    const float* __restrict__ bias, float* __restrict__ out)
{
    const int d = blockIdx.x;
    const int h = threadIdx.x >> 5, lane = threadIdx.x & 31;
    const int beg = g_off[d], end = g_off[d + 1];
    const int hc = h * 32 + lane;

    float acc0 = 0.f, acc1 = 0.f, acc2 = 0.f, acc3 = 0.f;
    float ss = 0.f;
    int i = beg;
    for (; i + 4 <= end; i += 4) {
        int s0 = g_esrc[i], s1 = g_esrc[i + 1], s2 = g_esrc[i + 2], s3 = g_esrc[i + 3];
        float p0 = pe[(size_t)i * 8 + h];
        float p1 = pe[(size_t)(i + 1) * 8 + h];
        float p2 = pe[(size_t)(i + 2) * 8 + h];
        float p3 = pe[(size_t)(i + 3) * 8 + h];
        float v0 = hl[(size_t)s0 * DD + hc];
        float v1 = hl[(size_t)s1 * DD + hc];
        float v2 = hl[(size_t)s2 * DD + hc];
        float v3 = hl[(size_t)s3 * DD + hc];
        ss += (p0 + p1) + (p2 + p3);
        acc0 = fmaf(p0, v0, acc0);
        acc1 = fmaf(p1, v1, acc1);
        acc2 = fmaf(p2, v2, acc2);
        acc3 = fmaf(p3, v3, acc3);
    }
    for (; i < end; i++) {
        int s0 = g_esrc[i];
        float p0 = pe[(size_t)i * 8 + h];
        ss += p0;
        acc0 = fmaf(p0, hl[(size_t)s0 * DD + hc], acc0);
    }
    float acc = (acc0 + acc1) + (acc2 + acc3);
    out[(size_t)d * DD + hc] = fmaxf(acc / ss + bias[hc], 0.f);
}

// ---------------- MMA flash-attention: 128 queries / CTA, no max-shift -----------
__global__ void __launch_bounds__(128) attn_mma_kernel(const float* __restrict__ qkv,
                                                       float* __restrict__ out)
{
    extern __shared__ __align__(16) float asm_[];
    float (*Qs)[36] = (float(*)[36])asm_;
    float (*Ks)[36] = (float(*)[36])(asm_ + 128 * 36);
    float (*Vt)[68] = (float(*)[68])(asm_ + 128 * 36 + 64 * 36);
    float (*Ps)[68] = (float(*)[68])(asm_ + 128 * 36 + 64 * 36 + 32 * 68);

    const int bh = blockIdx.x, b = bh >> 3, h = bh & 7;
    const int qt = blockIdx.y;
    const int tid = threadIdx.x;
    const int warp = tid >> 5, lane = tid & 31;
    const int lg = lane >> 2, lt = lane & 3;
    const float* base = qkv + (size_t)b * LL * 768;
    const float scale = 0.17677669529663687f;

#pragma unroll
    for (int i = 0; i < 8; i++) {
        int idx = tid + i * 128;
        int row = idx >> 3, c4 = (idx & 7) << 2;
        float4 v = *(const float4*)(base + (size_t)(qt * 128 + row) * 768 + h * 32 + c4);
        Qs[row][c4 + 0] = f2tf_f(v.x * scale);
        Qs[row][c4 + 1] = f2tf_f(v.y * scale);
        Qs[row][c4 + 2] = f2tf_f(v.z * scale);
        Qs[row][c4 + 3] = f2tf_f(v.w * scale);
    }

    float l[4] = {0.f, 0.f, 0.f, 0.f};
    float o[2][4][4];
#pragma unroll
    for (int mg = 0; mg < 2; mg++)
#pragma unroll
        for (int nt = 0; nt < 4; nt++)
#pragma unroll
            for (int r = 0; r < 4; r++) o[mg][nt][r] = 0.f;

    for (int kt = 0; kt < 16; kt++) {
        __syncthreads();
#pragma unroll
        for (int i = 0; i < 4; i++) {
            int idx = tid + i * 128;
            int row = idx >> 3, c4 = (idx & 7) << 2;
            const float* kp = base + (size_t)(kt * 64 + row) * 768 + 256 + h * 32 + c4;
            float4 kv = *(const float4*)kp;
            Ks[row][c4 + 0] = f2tf_f(kv.x);
            Ks[row][c4 + 1] = f2tf_f(kv.y);
            Ks[row][c4 + 2] = f2tf_f(kv.z);
            Ks[row][c4 + 3] = f2tf_f(kv.w);
            float4 vv = *(const float4*)(kp + 256);
            Vt[c4 + 0][row] = f2tf_f(vv.x);
            Vt[c4 + 1][row] = f2tf_f(vv.y);
            Vt[c4 + 2][row] = f2tf_f(vv.z);
            Vt[c4 + 3][row] = f2tf_f(vv.w);
        }
        __syncthreads();

#pragma unroll
        for (int mg = 0; mg < 2; mg++) {
            const int r0 = warp * 32 + mg * 16 + lg;
            float s[8][4];
#pragma unroll
            for (int nt = 0; nt < 8; nt++)
#pragma unroll
                for (int r = 0; r < 4; r++) s[nt][r] = 0.f;
#pragma unroll
            for (int kk = 0; kk < 4; kk++) {
                const int c = kk * 8 + lt;
                unsigned a[4];
                a[0] = __float_as_uint(Qs[r0][c]);
                a[1] = __float_as_uint(Qs[r0 + 8][c]);
                a[2] = __float_as_uint(Qs[r0][c + 4]);
                a[3] = __float_as_uint(Qs[r0 + 8][c + 4]);
#pragma unroll
                for (int nt = 0; nt < 8; nt++) {
                    unsigned bb[2];
                    bb[0] = __float_as_uint(Ks[nt * 8 + lg][c]);
                    bb[1] = __float_as_uint(Ks[nt * 8 + lg][c + 4]);
                    mma8(s[nt], a, bb);
                }
            }
            float ps0 = 0.f, ps1 = 0.f;
#pragma unroll
            for (int nt = 0; nt < 8; nt++) {
                float p0 = __expf(s[nt][0]);
                float p1 = __expf(s[nt][1]);
                float p2 = __expf(s[nt][2]);
                float p3 = __expf(s[nt][3]);
                ps0 += p0 + p1;
                ps1 += p2 + p3;
                int col = nt * 8 + (lt << 1);
                Ps[r0][col]     = f2tf_f(p0);
                Ps[r0][col + 1] = f2tf_f(p1);
                Ps[r0 + 8][col]     = f2tf_f(p2);
                Ps[r0 + 8][col + 1] = f2tf_f(p3);
            }
            l[mg * 2 + 0] += ps0;
            l[mg * 2 + 1] += ps1;
        }
        __syncwarp();

#pragma unroll
        for (int mg = 0; mg < 2; mg++) {
            const int r0 = warp * 32 + mg * 16 + lg;
#pragma unroll
            for (int kk = 0; kk < 8; kk++) {
                const int c = kk * 8 + lt;
                unsigned a[4];
                a[0] = __float_as_uint(Ps[r0][c]);
                a[1] = __float_as_uint(Ps[r0 + 8][c]);
                a[2] = __float_as_uint(Ps[r0][c + 4]);
                a[3] = __float_as_uint(Ps[r0 + 8][c + 4]);
#pragma unroll
                for (int nt = 0; nt < 4; nt++) {
                    unsigned bb[2];
                    bb[0] = __float_as_uint(Vt[nt * 8 + lg][c]);
                    bb[1] = __float_as_uint(Vt[nt * 8 + lg][c + 4]);
                    mma8(o[mg][nt], a, bb);
                }
            }
        }
    }

#pragma unroll
    for (int j = 0; j < 4; j++) {
        l[j] += __shfl_xor_sync(0xffffffffu, l[j], 1);
        l[j] += __shfl_xor_sync(0xffffffffu, l[j], 2);
    }

#pragma unroll
    for (int mg = 0; mg < 2; mg++) {
        float inv0 = 1.0f / l[mg * 2 + 0];
        float inv1 = 1.0f / l[mg * 2 + 1];
        int q0 = qt * 128 + warp * 32 + mg * 16 + lg;
        float* op = out + (size_t)(b * LL + q0) * DD + h * 32;
#pragma unroll
        for (int nt = 0; nt < 4; nt++) {
            int col = nt * 8 + (lt << 1);
            *(float2*)(op + col) = make_float2(o[mg][nt][0] * inv0, o[mg][nt][1] * inv0);
            *(float2*)(op + 8 * DD + col) = make_float2(o[mg][nt][2] * inv1, o[mg][nt][3] * inv1);
        }
    }
}

// ---------------- host orchestration ----------------
extern "C" void kernel_launch(void* const* d_in, const int* in_sizes, int n_in,
                              void* d_out, int out_size)
{
    const float* x        = (const float*)d_in[0];
    const int*   ei       = (const int*)  d_in[1];
    const float* gat_W0   = (const float*)d_in[3];
    const float* gat_W12  = (const float*)d_in[4];
    const float* att_src  = (const float*)d_in[5];
    const float* att_dst  = (const float*)d_in[6];
    const float* gat_bias = (const float*)d_in[7];
    const float* qkv_w    = (const float*)d_in[8];
    const float* qkv_b    = (const float*)d_in[9];
    const float* out_w    = (const float*)d_in[10];
    const float* out_b    = (const float*)d_in[11];
    const float* ln1_w    = (const float*)d_in[12];
    const float* ln1_b    = (const float*)d_in[13];
    const float* ln2_w    = (const float*)d_in[14];
    const float* ln2_b    = (const float*)d_in[15];
    const float* ff1_w    = (const float*)d_in[16];
    const float* ff1_b    = (const float*)d_in[17];
    const float* ff2_w    = (const float*)d_in[18];
    const float* ff2_b    = (const float*)d_in[19];
    const float* pred_w   = (const float*)d_in[20];
    const float* pred_b   = (const float*)d_in[21];

    const int E = in_sizes[1] / 2;
    const int Etot = E + NN;
    const int* src = ei;
    const int* dst = ei + E;

    float *hl, *h0, *h1, *as_, *ad_, *pe, *qkv, *attn, *ff, *wr;
    cudaGetSymbolAddress((void**)&hl,   g_hl);
    cudaGetSymbolAddress((void**)&h0,   g_h0);
    cudaGetSymbolAddress((void**)&h1,   g_h1);
    cudaGetSymbolAddress((void**)&as_,  g_as);
    cudaGetSymbolAddress((void**)&ad_,  g_ad);
    cudaGetSymbolAddress((void**)&pe,   g_pe);
    cudaGetSymbolAddress((void**)&qkv,  g_qkv);
    cudaGetSymbolAddress((void**)&attn, g_attn);
    cudaGetSymbolAddress((void**)&ff,   g_ff);
    cudaGetSymbolAddress((void**)&wr,   g_wr);

    float* W0r  = wr;
    float* W12r = W0r  + W0_N;
    float* qwr  = W12r + W12_N;
    float* owr  = qwr  + QW_N;
    float* f1r  = owr  + OW_N;
    float* f2r  = f1r  + F1_N;

    cudaFuncSetAttribute(tgemm_kernel<1>, cudaFuncAttributeMaxDynamicSharedMemorySize, TG_SMEM2);
    cudaFuncSetAttribute(tgemm_kernel<2>, cudaFuncAttributeMaxDynamicSharedMemorySize, TG_SMEM2);
    cudaFuncSetAttribute(tgemm_kernel<3>, cudaFuncAttributeMaxDynamicSharedMemorySize, TG_SMEM2);
    cudaFuncSetAttribute(tgemm_ln_kernel<0>, cudaFuncAttributeMaxDynamicSharedMemorySize, TL_SMEM3);
    cudaFuncSetAttribute(tgemm_ln_kernel<1>, cudaFuncAttributeMaxDynamicSharedMemorySize, TL_SMEM3);
    cudaFuncSetAttribute(attn_mma_kernel, cudaFuncAttributeMaxDynamicSharedMemorySize, AT_SMEM);

    // pre-round all weights to tf32 (rna) in one launch
    round_all_kernel<<<(WR_N / 4 + 255) / 256, 256>>>(gat_W0, gat_W12, qkv_w, out_w,
                                                      ff1_w, ff2_w, wr);

    const int eb = (Etot + 255) / 256;

    // CSR build (once)
    csr_zero_kernel<<<(NN + 255) / 256, 256>>>();
    csr_hist_kernel<<<eb, 256>>>(dst, E, Etot);
    csr_scan_kernel<<<1, 1024>>>();
    csr_fill_kernel<<<eb, 256>>>(src, dst, E, Etot);

    auto gat_layer = [&](const float* in, int Din, const float* W,
                         const float* atts, const float* attd, const float* bias,
                         float* outp) {
        tgemm_kernel<3><<<dim3(DD / 128, NN / 128), 256, TG_SMEM2>>>(
            in, W, nullptr, hl, NN, DD, Din, atts, attd, as_, ad_);
        gat_edge_p_kernel<<<eb, 256>>>(Etot, as_, ad_, pe);
        gat_gather_kernel<<<NN, 256>>>(hl, pe, bias, outp);
    };

    gat_layer(x,  INC, W0r,             att_src,           att_dst,           gat_bias,          h0);
    gat_layer(h0, DD,  W12r,            att_src + HH * CC, att_dst + HH * CC, gat_bias + DD,     h1);
    gat_layer(h1, DD,  W12r + DD * DD,  att_src + 2*HH*CC, att_dst + 2*HH*CC, gat_bias + 2 * DD, h0);

    for (int l = 0; l < 2; l++) {
        const float* qw  = qwr + (size_t)l * 3 * DD * DD;
        const float* qb  = qkv_b + l * 3 * DD;
        const float* ow  = owr + (size_t)l * DD * DD;
        const float* ob  = out_b + l * DD;
        const float* l1w = ln1_w + l * DD, * l1b = ln1_b + l * DD;
        const float* l2w = ln2_w + l * DD, * l2b = ln2_b + l * DD;
        const float* f1w = f1r + (size_t)l * DFF * DD;
        const float* f1b = ff1_b + l * DFF;
        const float* f2w = f2r + (size_t)l * DD * DFF;
        const float* f2b = ff2_b + l * DD;

        tgemm_kernel<1><<<dim3(3 * DD / 128, NN / 128), 256, TG_SMEM2>>>(
            h0, qw, qb, qkv, NN, 3 * DD, DD, nullptr, nullptr, nullptr, nullptr);
        attn_mma_kernel<<<dim3(BB * HH, LL / 128), 128, AT_SMEM>>>(qkv, attn);
        tgemm_ln_kernel<0><<<dim3(1, NN / 64), 256, TL_SMEM3>>>(
            attn, ow, ob, h0, l1w, l1b, h1, NN, DD, nullptr, nullptr, nullptr);
        tgemm_kernel<2><<<dim3(DFF / 128, NN / 128), 256, TG_SMEM2>>>(
            h1, f1w, f1b, ff, NN, DFF, DD, nullptr, nullptr, nullptr, nullptr);
        if (l == 0) {
            tgemm_ln_kernel<0><<<dim3(1, NN / 64), 256, TL_SMEM3>>>(
                ff, f2w, f2b, h1, l2w, l2b, h0, NN, DFF, nullptr, nullptr, nullptr);
        } else {
            // final layer: fuse prediction head; Y store skipped
            tgemm_ln_kernel<1><<<dim3(1, NN / 64), 256, TL_SMEM3>>>(
                ff, f2w, f2b, h1, l2w, l2b, h0, NN, DFF, pred_w, pred_b, (float*)d_out);
        }
    }
}

// round 17
// speedup vs baseline: 1.0483x; 1.0131x over previous
#include <cuda_runtime.h>
#include <math.h>
#include <stdint.h>

#define NN   8192
#define BB   8
#define LL   1024
#define INC  64
#define HH   8
#define CC   32
#define DD   256
#define DFF  2048
#define EMAX 262144
#define ETOTMAX (EMAX + NN)

#define TG_STG   (256 * 36)
#define TG_SMEM2 (2 * TG_STG * 4)        // 73728 B -> 2 CTAs/SM
#define TL_STG   (320 * 36)
#define TL_SMEM3 (3 * TL_STG * 4)

// attention smem (dynamic): Qs 128x36 + Ks 64x36 + Vt 32x68 + Ps 128x68
#define AT_SMEM ((128 * 36 + 64 * 36 + 32 * 68 + 128 * 68) * 4)

// pre-rounded weight scratch sizes (floats)
#define W0_N   (DD * INC)
#define W12_N  (2 * DD * DD)
#define QW_N   (2 * 3 * DD * DD)
#define OW_N   (2 * DD * DD)
#define F1_N   (2 * DFF * DD)
#define F2_N   (2 * DD * DFF)
#define WR_N   (W0_N + W12_N + QW_N + OW_N + F1_N + F2_N)

// ---------------- scratch (device globals; no runtime allocation) ----------------
__device__ float g_hl  [NN * DD];
__device__ float g_h0  [NN * DD];
__device__ float g_h1  [NN * DD];
__device__ float g_as  [NN * HH];
__device__ float g_ad  [NN * HH];
__device__ float g_pe  [ETOTMAX * HH];
__device__ float g_qkv [NN * 3 * DD];
__device__ float g_attn[NN * DD];
__device__ float g_ff  [NN * DFF];
__device__ float g_wr  [WR_N];
// CSR (built once per launch)
__device__ int   g_deg [NN];
__device__ int   g_off [NN + 1];
__device__ int   g_pos [NN];
__device__ int   g_esrc[ETOTMAX];
__device__ int   g_edst[ETOTMAX];

// ---------------- helpers ----------------
__device__ __forceinline__ float f2tf_f(float f) {
    unsigned u;
    asm("cvt.rna.tf32.f32 %0, %1;" : "=r"(u) : "f"(f));
    return __uint_as_float(u);
}

__device__ __forceinline__ unsigned f2tf_u(float f) {
    unsigned u;
    asm("cvt.rna.tf32.f32 %0, %1;" : "=r"(u) : "f"(f));
    return u;
}

__device__ __forceinline__ void mma8(float* d, const unsigned* a, const unsigned* b) {
    asm volatile(
        "mma.sync.aligned.m16n8k8.row.col.f32.tf32.tf32.f32 "
        "{%0,%1,%2,%3},{%4,%5,%6,%7},{%8,%9},{%0,%1,%2,%3};"
        : "+f"(d[0]), "+f"(d[1]), "+f"(d[2]), "+f"(d[3])
        : "r"(a[0]), "r"(a[1]), "r"(a[2]), "r"(a[3]), "r"(b[0]), "r"(b[1]));
}

#define CP16(dst_u32, src_ptr) \
    asm volatile("cp.async.cg.shared.global [%0], [%1], 16;\n" :: "r"(dst_u32), "l"(src_ptr))
#define CP_COMMIT() asm volatile("cp.async.commit_group;\n" ::)
#define CP_WAIT1()  asm volatile("cp.async.wait_group 1;\n" ::)

// ---------------- merged tf32 pre-round + g_deg zero (once per launch) ----------
__global__ void round_all_kernel(const float* __restrict__ s0, const float* __restrict__ s1,
                                 const float* __restrict__ s2, const float* __restrict__ s3,
                                 const float* __restrict__ s4, const float* __restrict__ s5,
                                 float* __restrict__ dst)
{
    int i = blockIdx.x * blockDim.x + threadIdx.x;   // float4 index
    if (i < NN / 4) ((int4*)g_deg)[i] = make_int4(0, 0, 0, 0);
    if (i >= WR_N / 4) return;
    int f = i * 4;
    const float* src;
    int off;
    if (f < W0_N)                                  { src = s0; off = f; }
    else if (f < W0_N + W12_N)                     { src = s1; off = f - W0_N; }
    else if (f < W0_N + W12_N + QW_N)              { src = s2; off = f - (W0_N + W12_N); }
    else if (f < W0_N + W12_N + QW_N + OW_N)       { src = s3; off = f - (W0_N + W12_N + QW_N); }
    else if (f < W0_N + W12_N + QW_N + OW_N + F1_N){ src = s4; off = f - (W0_N + W12_N + QW_N + OW_N); }
    else                                           { src = s5; off = f - (W0_N + W12_N + QW_N + OW_N + F1_N); }
    float4 v = *(const float4*)(src + off);
    v.x = f2tf_f(v.x); v.y = f2tf_f(v.y);
    v.z = f2tf_f(v.z); v.w = f2tf_f(v.w);
    ((float4*)dst)[i] = v;
}

// ---------------- cp.async 2-stage tensor-core GEMM (2 CTAs/SM) -------------------
// BIASMODE: 1 bias, 2 bias+relu, 3 GAT (no bias/relu; fused coef dot)
template<int BIASMODE>
__global__ void __launch_bounds__(256, 2) tgemm_kernel(
    const float* __restrict__ A, const float* __restrict__ W,
    const float* __restrict__ bias, float* __restrict__ C,
    int M, int Nn, int K,
    const float* __restrict__ atts, const float* __restrict__ attd,
    float* __restrict__ asv, float* __restrict__ adv)
{
    extern __shared__ __align__(16) float sm[];
    unsigned sbase = (unsigned)__cvta_generic_to_shared(sm);

    const int bm = blockIdx.y * 128;
    const int bn = blockIdx.x * 128;
    const int tid = threadIdx.x;
    const int warp = tid >> 5, lane = tid & 31;
    const int wm = warp & 3, wn = warp >> 2;
    const int lg = lane >> 2, lt = lane & 3;

    int lrow[4], lc4[4];
#pragma unroll
    for (int i = 0; i < 4; i++) {
        int f4 = tid + i * 256;
        lrow[i] = f4 >> 3;
        lc4[i] = (f4 & 7) << 2;
    }

    float acc[2][8][4];
#pragma unroll
    for (int mt = 0; mt < 2; mt++)
#pragma unroll
        for (int nt = 0; nt < 8; nt++)
#pragma unroll
            for (int r = 0; r < 4; r++) acc[mt][nt][r] = 0.0f;

    const int nk = K >> 5;
    auto issue = [&](int t) {
        if (t < nk) {
            int k0 = t << 5;
            unsigned so = sbase + (unsigned)((t & 1) * TG_STG) * 4u;
#pragma unroll
            for (int i = 0; i < 4; i++) {
                const float* gA = A + (size_t)(bm + lrow[i]) * K + k0 + lc4[i];
                const float* gB = W + (size_t)(bn + lrow[i]) * K + k0 + lc4[i];
                CP16(so + (unsigned)(lrow[i] * 36 + lc4[i]) * 4u, gA);
                CP16(so + (unsigned)((128 * 36) + lrow[i] * 36 + lc4[i]) * 4u, gB);
            }
        }
        CP_COMMIT();
    };

    issue(0);
    for (int t = 0; t < nk; t++) {
        issue(t + 1);
        CP_WAIT1();
        __syncthreads();
        const float* As = sm + (t & 1) * TG_STG;
        const float* Bs = As + 128 * 36;
#pragma unroll
        for (int kk = 0; kk < 32; kk += 8) {
            unsigned ah[2][4], bf[8][2];
            const int c = kk + lt;
#pragma unroll
            for (int mt = 0; mt < 2; mt++) {
                int r = wm * 32 + mt * 16 + lg;
                ah[mt][0] = f2tf_u(As[r * 36 + c]);
                ah[mt][1] = f2tf_u(As[(r + 8) * 36 + c]);
                ah[mt][2] = f2tf_u(As[r * 36 + c + 4]);
                ah[mt][3] = f2tf_u(As[(r + 8) * 36 + c + 4]);
            }
#pragma unroll
            for (int nt = 0; nt < 8; nt++) {
                int n = wn * 64 + nt * 8 + lg;
                bf[nt][0] = __float_as_uint(Bs[n * 36 + c]);
                bf[nt][1] = __float_as_uint(Bs[n * 36 + c + 4]);
            }
#pragma unroll
            for (int mt = 0; mt < 2; mt++)
#pragma unroll
                for (int nt = 0; nt < 8; nt++)
                    mma8(acc[mt][nt], ah[mt], bf[nt]);
        }
        __syncthreads();
    }

    // fused GAT coef partials: [mt][rowhalf][head-in-warp(2)]
    float aS[2][2][2], aD[2][2][2];
    if (BIASMODE == 3) {
#pragma unroll
        for (int a = 0; a < 2; a++)
#pragma unroll
            for (int b2 = 0; b2 < 2; b2++)
#pragma unroll
                for (int c2 = 0; c2 < 2; c2++) { aS[a][b2][c2] = 0.f; aD[a][b2][c2] = 0.f; }
    }

#pragma unroll
    for (int mt = 0; mt < 2; mt++) {
#pragma unroll
        for (int nt = 0; nt < 8; nt++) {
            int row = bm + wm * 32 + mt * 16 + lg;
            int col = bn + wn * 64 + nt * 8 + (lt << 1);
            float b0 = 0.f, b1 = 0.f;
            if (BIASMODE == 1 || BIASMODE == 2) { b0 = bias[col]; b1 = bias[col + 1]; }
            float v0 = acc[mt][nt][0] + b0, v1 = acc[mt][nt][1] + b1;
            float v2 = acc[mt][nt][2] + b0, v3 = acc[mt][nt][3] + b1;
            if (BIASMODE == 2) {
                v0 = fmaxf(v0, 0.f); v1 = fmaxf(v1, 0.f);
                v2 = fmaxf(v2, 0.f); v3 = fmaxf(v3, 0.f);
            }
            if (BIASMODE == 3) {
                int hs = nt >> 2;
                float2 ts = *(const float2*)&atts[col];
                float2 td = *(const float2*)&attd[col];
                aS[mt][0][hs] += v0 * ts.x + v1 * ts.y;
                aS[mt][1][hs] += v2 * ts.x + v3 * ts.y;
                aD[mt][0][hs] += v0 * td.x + v1 * td.y;
                aD[mt][1][hs] += v2 * td.x + v3 * td.y;
            }
            *(float2*)&C[(size_t)row * Nn + col] = make_float2(v0, v1);
            *(float2*)&C[(size_t)(row + 8) * Nn + col] = make_float2(v2, v3);
        }
    }

    if (BIASMODE == 3) {
#pragma unroll
        for (int mt = 0; mt < 2; mt++)
#pragma unroll
            for (int hf = 0; hf < 2; hf++)
#pragma unroll
                for (int hs = 0; hs < 2; hs++) {
                    float s = aS[mt][hf][hs], d = aD[mt][hf][hs];
                    s += __shfl_xor_sync(0xffffffffu, s, 1);
                    s += __shfl_xor_sync(0xffffffffu, s, 2);
                    d += __shfl_xor_sync(0xffffffffu, d, 1);
                    d += __shfl_xor_sync(0xffffffffu, d, 2);
                    aS[mt][hf][hs] = s; aD[mt][hf][hs] = d;
                }
        if (lt == 0) {
            int headbase = (bn + wn * 64) >> 5;
#pragma unroll
            for (int mt = 0; mt < 2; mt++)
#pragma unroll
                for (int hf = 0; hf < 2; hf++) {
                    int row = bm + wm * 32 + mt * 16 + lg + hf * 8;
#pragma unroll
                    for (int hs = 0; hs < 2; hs++) {
                        asv[row * 8 + headbase + hs] = aS[mt][hf][hs];
                        adv[row * 8 + headbase + hs] = aD[mt][hf][hs];
                    }
                }
        }
    }
}

// ---------------- GEMM + residual + LayerNorm fused (BM=64, BN=256, 3-stage) ----
// PRED=1: additionally compute final prediction; Y store skipped.
template<int PRED>
__global__ void __launch_bounds__(256) tgemm_ln_kernel(
    const float* __restrict__ A, const float* __restrict__ W,
    const float* __restrict__ bias, const float* __restrict__ res,
    const float* __restrict__ lnw, const float* __restrict__ lnb,
    float* __restrict__ Y, int M, int K,
    const float* __restrict__ pw, const float* __restrict__ pb,
    float* __restrict__ pout)
{
    extern __shared__ __align__(16) float sm[];
    unsigned sbase = (unsigned)__cvta_generic_to_shared(sm);

    const int bm = blockIdx.y * 64;
    const int tid = threadIdx.x;
    const int warp = tid >> 5, lane = tid & 31;
    const int wm = warp & 1, wn = warp >> 1;
    const int lg = lane >> 2, lt = lane & 3;

    int arow[2], ac4[2], brow[8], bc4[8];
#pragma unroll
    for (int i = 0; i < 2; i++) {
        int f4 = tid + i * 256;
        arow[i] = f4 >> 3; ac4[i] = (f4 & 7) << 2;
    }
#pragma unroll
    for (int i = 0; i < 8; i++) {
        int f4 = tid + i * 256;
        brow[i] = f4 >> 3; bc4[i] = (f4 & 7) << 2;
    }

    float acc[2][8][4];
#pragma unroll
    for (int mt = 0; mt < 2; mt++)
#pragma unroll
        for (int nt = 0; nt < 8; nt++)
#pragma unroll
            for (int r = 0; r < 4; r++) acc[mt][nt][r] = 0.0f;

    const int nk = K >> 5;
    auto issue = [&](int t) {
        if (t < nk) {
            int k0 = t << 5;
            unsigned so = sbase + (unsigned)((t % 3) * TL_STG) * 4u;
#pragma unroll
            for (int i = 0; i < 2; i++) {
                const float* gA = A + (size_t)(bm + arow[i]) * K + k0 + ac4[i];
                CP16(so + (unsigned)(arow[i] * 36 + ac4[i]) * 4u, gA);
            }
#pragma unroll
            for (int i = 0; i < 8; i++) {
                const float* gB = W + (size_t)brow[i] * K + k0 + bc4[i];
                CP16(so + (unsigned)((64 * 36) + brow[i] * 36 + bc4[i]) * 4u, gB);
            }
        }
        CP_COMMIT();
    };

    issue(0); issue(1);
    for (int t = 0; t < nk; t++) {
        CP_WAIT1();
        __syncthreads();
        issue(t + 2);
        const float* As = sm + (t % 3) * TL_STG;
        const float* Bs = As + 64 * 36;
#pragma unroll
        for (int kk = 0; kk < 32; kk += 8) {
            unsigned ah[2][4], bf[8][2];
            const int c = kk + lt;
#pragma unroll
            for (int mt = 0; mt < 2; mt++) {
                int r = wm * 32 + mt * 16 + lg;
                ah[mt][0] = f2tf_u(As[r * 36 + c]);
                ah[mt][1] = f2tf_u(As[(r + 8) * 36 + c]);
                ah[mt][2] = f2tf_u(As[r * 36 + c + 4]);
                ah[mt][3] = f2tf_u(As[(r + 8) * 36 + c + 4]);
            }
#pragma unroll
            for (int nt = 0; nt < 8; nt++) {
                int n = wn * 64 + nt * 8 + lg;
                bf[nt][0] = __float_as_uint(Bs[n * 36 + c]);
                bf[nt][1] = __float_as_uint(Bs[n * 36 + c + 4]);
            }
#pragma unroll
            for (int mt = 0; mt < 2; mt++)
#pragma unroll
                for (int nt = 0; nt < 8; nt++)
                    mma8(acc[mt][nt], ah[mt], bf[nt]);
        }
    }

    __syncthreads();
    float* partS = sm;                 // [4][64]
    float* partQ = sm + 256;           // [4][64]
    float* pwsm  = sm + 512;           // [3][256] (PRED only)
    float* partP = sm + 512 + 768;     // [4][64][3] (PRED only)

    if (PRED) {
        for (int i = tid; i < 3 * DD; i += 256) pwsm[i] = pw[i];
    }

    float rs[4] = {0.f, 0.f, 0.f, 0.f}, rq[4] = {0.f, 0.f, 0.f, 0.f};
#pragma unroll
    for (int mt = 0; mt < 2; mt++) {
        int rl = wm * 32 + mt * 16 + lg;
#pragma unroll
        for (int nt = 0; nt < 8; nt++) {
            int col = wn * 64 + nt * 8 + (lt << 1);
            float2 bb = *(const float2*)&bias[col];
            float2 ra = *(const float2*)&res[(size_t)(bm + rl) * DD + col];
            float2 rb = *(const float2*)&res[(size_t)(bm + rl + 8) * DD + col];
            acc[mt][nt][0] += bb.x + ra.x;
            acc[mt][nt][1] += bb.y + ra.y;
            acc[mt][nt][2] += bb.x + rb.x;
            acc[mt][nt][3] += bb.y + rb.y;
            rs[mt * 2 + 0] += acc[mt][nt][0] + acc[mt][nt][1];
            rq[mt * 2 + 0] += acc[mt][nt][0] * acc[mt][nt][0] + acc[mt][nt][1] * acc[mt][nt][1];
            rs[mt * 2 + 1] += acc[mt][nt][2] + acc[mt][nt][3];
            rq[mt * 2 + 1] += acc[mt][nt][2] * acc[mt][nt][2] + acc[mt][nt][3] * acc[mt][nt][3];
        }
    }
#pragma unroll
    for (int j = 0; j < 4; j++) {
        rs[j] += __shfl_xor_sync(0xffffffffu, rs[j], 1);
        rs[j] += __shfl_xor_sync(0xffffffffu, rs[j], 2);
        rq[j] += __shfl_xor_sync(0xffffffffu, rq[j], 1);
        rq[j] += __shfl_xor_sync(0xffffffffu, rq[j], 2);
    }
    if (lt == 0) {
#pragma unroll
        for (int mt = 0; mt < 2; mt++)
#pragma unroll
            for (int i = 0; i < 2; i++) {
                int row = wm * 32 + mt * 16 + lg + i * 8;
                partS[wn * 64 + row] = rs[mt * 2 + i];
                partQ[wn * 64 + row] = rq[mt * 2 + i];
            }
    }
    __syncthreads();

    float pr[2][2][3];
    if (PRED) {
#pragma unroll
        for (int a = 0; a < 2; a++)
#pragma unroll
            for (int b2 = 0; b2 < 2; b2++)
#pragma unroll
                for (int j = 0; j < 3; j++) pr[a][b2][j] = 0.f;
    }

#pragma unroll
    for (int mt = 0; mt < 2; mt++) {
        int rl = wm * 32 + mt * 16 + lg;
        float mu[2], inv[2];
#pragma unroll
        for (int i = 0; i < 2; i++) {
            int row = rl + i * 8;
            float S = partS[row] + partS[64 + row] + partS[128 + row] + partS[192 + row];
            float Q = partQ[row] + partQ[64 + row] + partQ[128 + row] + partQ[192 + row];
            mu[i] = S * (1.0f / DD);
            float var = Q * (1.0f / DD) - mu[i] * mu[i];
            inv[i] = rsqrtf(var + 1e-5f);
        }
#pragma unroll
        for (int nt = 0; nt < 8; nt++) {
            int col = wn * 64 + nt * 8 + (lt << 1);
            float2 wv = *(const float2*)&lnw[col];
            float2 bv = *(const float2*)&lnb[col];
            float y0 = (acc[mt][nt][0] - mu[0]) * inv[0] * wv.x + bv.x;
            float y1 = (acc[mt][nt][1] - mu[0]) * inv[0] * wv.y + bv.y;
            float y2 = (acc[mt][nt][2] - mu[1]) * inv[1] * wv.x + bv.x;
            float y3 = (acc[mt][nt][3] - mu[1]) * inv[1] * wv.y + bv.y;
            if (PRED) {
#pragma unroll
                for (int j = 0; j < 3; j++) {
                    float w0 = pwsm[j * DD + col], w1 = pwsm[j * DD + col + 1];
                    pr[mt][0][j] += y0 * w0 + y1 * w1;
                    pr[mt][1][j] += y2 * w0 + y3 * w1;
                }
            } else {
                *(float2*)&Y[(size_t)(bm + rl) * DD + col] = make_float2(y0, y1);
                *(float2*)&Y[(size_t)(bm + rl + 8) * DD + col] = make_float2(y2, y3);
            }
        }
    }

    if (PRED) {
#pragma unroll
        for (int mt = 0; mt < 2; mt++)
#pragma unroll
            for (int hf = 0; hf < 2; hf++)
#pragma unroll
                for (int j = 0; j < 3; j++) {
                    float v = pr[mt][hf][j];
                    v += __shfl_xor_sync(0xffffffffu, v, 1);
                    v += __shfl_xor_sync(0xffffffffu, v, 2);
                    pr[mt][hf][j] = v;
                }
        if (lt == 0) {
#pragma unroll
            for (int mt = 0; mt < 2; mt++)
#pragma unroll
                for (int hf = 0; hf < 2; hf++) {
                    int row = wm * 32 + mt * 16 + lg + hf * 8;
#pragma unroll
                    for (int j = 0; j < 3; j++)
                        partP[(wn * 64 + row) * 3 + j] = pr[mt][hf][j];
                }
        }
        __syncthreads();
        if (tid < 64) {
#pragma unroll
            for (int j = 0; j < 3; j++) {
                float v = partP[(0 * 64 + tid) * 3 + j] + partP[(1 * 64 + tid) * 3 + j]
                        + partP[(2 * 64 + tid) * 3 + j] + partP[(3 * 64 + tid) * 3 + j];
                pout[(size_t)(bm + tid) * 3 + j] = v + pb[j];
            }
        }
    }
}

// ---------------- CSR build (once per launch) ----------------
__global__ void csr_hist_kernel(const int* __restrict__ dst, int E, int Etot) {
    int e = blockIdx.x * blockDim.x + threadIdx.x;
    if (e >= Etot) return;
    int d = (e < E) ? dst[e] : (e - E);
    atomicAdd(&g_deg[d], 1);
}

// warp-shuffle scan, vectorized int4 loads/stores (coalesced)
__global__ void __launch_bounds__(1024) csr_scan_kernel() {
    __shared__ int wsum[32];
    int t = threadIdx.x;
    int lane = t & 31, w = t >> 5;
    int4 d0 = ((const int4*)g_deg)[t * 2];
    int4 d1 = ((const int4*)g_deg)[t * 2 + 1];
    int local[8];
    int s = 0;
    local[0] = s; s += d0.x;
    local[1] = s; s += d0.y;
    local[2] = s; s += d0.z;
    local[3] = s; s += d0.w;
    local[4] = s; s += d1.x;
    local[5] = s; s += d1.y;
    local[6] = s; s += d1.z;
    local[7] = s; s += d1.w;
    int v = s;
#pragma unroll
    for (int off = 1; off < 32; off <<= 1) {
        int u = __shfl_up_sync(0xffffffffu, v, off);
        if (lane >= off) v += u;
    }
    if (lane == 31) wsum[w] = v;
    __syncthreads();
    if (w == 0) {
        int x = wsum[lane];
#pragma unroll
        for (int off = 1; off < 32; off <<= 1) {
            int u = __shfl_up_sync(0xffffffffu, x, off);
            if (lane >= off) x += u;
        }
        wsum[lane] = x;
    }
    __syncthreads();
    int prefix = v - s + ((w > 0) ? wsum[w - 1] : 0);
    int4 o0 = make_int4(prefix + local[0], prefix + local[1], prefix + local[2], prefix + local[3]);
    int4 o1 = make_int4(prefix + local[4], prefix + local[5], prefix + local[6], prefix + local[7]);
    ((int4*)g_off)[t * 2]     = o0;
    ((int4*)g_off)[t * 2 + 1] = o1;
    ((int4*)g_pos)[t * 2]     = o0;
    ((int4*)g_pos)[t * 2 + 1] = o1;
    if (t == 1023) g_off[NN] = wsum[31];
}

__global__ void csr_fill_kernel(const int* __restrict__ src, const int* __restrict__ dst,
                                int E, int Etot) {
    int e = blockIdx.x * blockDim.x + threadIdx.x;
    if (e >= Etot) return;
    int s, d;
    if (e < E) { s = src[e]; d = dst[e]; } else { s = d = e - E; }
    int p = atomicAdd(&g_pos[d], 1);
    g_esrc[p] = s;
    g_edst[p] = d;
}

// ---------------- GAT edge/gather kernels (R14-proven) ----------------
__global__ void gat_edge_p_kernel(int Etot,
                                  const float* __restrict__ as_,
                                  const float* __restrict__ ad_,
                                  float* __restrict__ pe)
{
    int i = blockIdx.x * blockDim.x + threadIdx.x;
    if (i >= Etot) return;
    int s = g_esrc[i], d = g_edst[i];
    float4 s0 = *(const float4*)&as_[s * 8];
    float4 s1 = *(const float4*)&as_[s * 8 + 4];
    float4 d0 = *(const float4*)&ad_[d * 8];
    float4 d1 = *(const float4*)&ad_[d * 8 + 4];
    float a[8] = {s0.x + d0.x, s0.y + d0.y, s0.z + d0.z, s0.w + d0.w,
                  s1.x + d1.x, s1.y + d1.y, s1.z + d1.z, s1.w + d1.w};
#pragma unroll
    for (int h = 0; h < 8; h++) {
        float t = a[h];
        t = (t > 0.f) ? t : 0.2f * t;
        a[h] = __expf(t);
    }
    *(float4*)&pe[(size_t)i * 8]     = make_float4(a[0], a[1], a[2], a[3]);
    *(float4*)&pe[(size_t)i * 8 + 4] = make_float4(a[4], a[5], a[6], a[7]);
}

__global__ void __launch_bounds__(256) gat_gather_kernel(
    const float* __restrict__ hl, const float* __restrict__ pe,
    const float* __restrict__ bias, float* __restrict__ out)
{
    const int d = blockIdx.x;
    const int h = threadIdx.x >> 5, lane = threadIdx.x & 31;
    const int beg = g_off[d], end = g_off[d + 1];
    const int hc = h * 32 + lane;

    float acc0 = 0.f, acc1 = 0.f, acc2 = 0.f, acc3 = 0.f;
    float ss = 0.f;
    int i = beg;
    for (; i + 4 <= end; i += 4) {
        int s0 = g_esrc[i], s1 = g_esrc[i + 1], s2 = g_esrc[i + 2], s3 = g_esrc[i + 3];
        float p0 = pe[(size_t)i * 8 + h];
        float p1 = pe[(size_t)(i + 1) * 8 + h];
        float p2 = pe[(size_t)(i + 2) * 8 + h];
        float p3 = pe[(size_t)(i + 3) * 8 + h];
        float v0 = hl[(size_t)s0 * DD + hc];
        float v1 = hl[(size_t)s1 * DD + hc];
        float v2 = hl[(size_t)s2 * DD + hc];
        float v3 = hl[(size_t)s3 * DD + hc];
        ss += (p0 + p1) + (p2 + p3);
        acc0 = fmaf(p0, v0, acc0);
        acc1 = fmaf(p1, v1, acc1);
        acc2 = fmaf(p2, v2, acc2);
        acc3 = fmaf(p3, v3, acc3);
    }
    for (; i < end; i++) {
        int s0 = g_esrc[i];
        float p0 = pe[(size_t)i * 8 + h];
        ss += p0;
        acc0 = fmaf(p0, hl[(size_t)s0 * DD + hc], acc0);
    }
    float acc = (acc0 + acc1) + (acc2 + acc3);
    out[(size_t)d * DD + hc] = fmaxf(acc / ss + bias[hc], 0.f);
}

// ---------------- MMA flash-attention: 128 queries / CTA, no max-shift -----------
__global__ void __launch_bounds__(128) attn_mma_kernel(const float* __restrict__ qkv,
                                                       float* __restrict__ out)
{
    extern __shared__ __align__(16) float asm_[];
    float (*Qs)[36] = (float(*)[36])asm_;
    float (*Ks)[36] = (float(*)[36])(asm_ + 128 * 36);
    float (*Vt)[68] = (float(*)[68])(asm_ + 128 * 36 + 64 * 36);
    float (*Ps)[68] = (float(*)[68])(asm_ + 128 * 36 + 64 * 36 + 32 * 68);

    const int bh = blockIdx.x, b = bh >> 3, h = bh & 7;
    const int qt = blockIdx.y;
    const int tid = threadIdx.x;
    const int warp = tid >> 5, lane = tid & 31;
    const int lg = lane >> 2, lt = lane & 3;
    const float* base = qkv + (size_t)b * LL * 768;
    const float scale = 0.17677669529663687f;

#pragma unroll
    for (int i = 0; i < 8; i++) {
        int idx = tid + i * 128;
        int row = idx >> 3, c4 = (idx & 7) << 2;
        float4 v = *(const float4*)(base + (size_t)(qt * 128 + row) * 768 + h * 32 + c4);
        Qs[row][c4 + 0] = f2tf_f(v.x * scale);
        Qs[row][c4 + 1] = f2tf_f(v.y * scale);
        Qs[row][c4 + 2] = f2tf_f(v.z * scale);
        Qs[row][c4 + 3] = f2tf_f(v.w * scale);
    }

    float l[4] = {0.f, 0.f, 0.f, 0.f};
    float o[2][4][4];
#pragma unroll
    for (int mg = 0; mg < 2; mg++)
#pragma unroll
        for (int nt = 0; nt < 4; nt++)
#pragma unroll
            for (int r = 0; r < 4; r++) o[mg][nt][r] = 0.f;

    for (int kt = 0; kt < 16; kt++) {
        __syncthreads();
#pragma unroll
        for (int i = 0; i < 4; i++) {
            int idx = tid + i * 128;
            int row = idx >> 3, c4 = (idx & 7) << 2;
            const float* kp = base + (size_t)(kt * 64 + row) * 768 + 256 + h * 32 + c4;
            float4 kv = *(const float4*)kp;
            Ks[row][c4 + 0] = f2tf_f(kv.x);
            Ks[row][c4 + 1] = f2tf_f(kv.y);
            Ks[row][c4 + 2] = f2tf_f(kv.z);
            Ks[row][c4 + 3] = f2tf_f(kv.w);
            float4 vv = *(const float4*)(kp + 256);
            Vt[c4 + 0][row] = f2tf_f(vv.x);
            Vt[c4 + 1][row] = f2tf_f(vv.y);
            Vt[c4 + 2][row] = f2tf_f(vv.z);
            Vt[c4 + 3][row] = f2tf_f(vv.w);
        }
        __syncthreads();

#pragma unroll
        for (int mg = 0; mg < 2; mg++) {
            const int r0 = warp * 32 + mg * 16 + lg;
            float s[8][4];
#pragma unroll
            for (int nt = 0; nt < 8; nt++)
#pragma unroll
                for (int r = 0; r < 4; r++) s[nt][r] = 0.f;
#pragma unroll
            for (int kk = 0; kk < 4; kk++) {
                const int c = kk * 8 + lt;
                unsigned a[4];
                a[0] = __float_as_uint(Qs[r0][c]);
                a[1] = __float_as_uint(Qs[r0 + 8][c]);
                a[2] = __float_as_uint(Qs[r0][c + 4]);
                a[3] = __float_as_uint(Qs[r0 + 8][c + 4]);
#pragma unroll
                for (int nt = 0; nt < 8; nt++) {
                    unsigned bb[2];
                    bb[0] = __float_as_uint(Ks[nt * 8 + lg][c]);
                    bb[1] = __float_as_uint(Ks[nt * 8 + lg][c + 4]);
                    mma8(s[nt], a, bb);
                }
            }
            float ps0 = 0.f, ps1 = 0.f;
#pragma unroll
            for (int nt = 0; nt < 8; nt++) {
                float p0 = __expf(s[nt][0]);
                float p1 = __expf(s[nt][1]);
                float p2 = __expf(s[nt][2]);
                float p3 = __expf(s[nt][3]);
                ps0 += p0 + p1;
                ps1 += p2 + p3;
                int col = nt * 8 + (lt << 1);
                Ps[r0][col]     = f2tf_f(p0);
                Ps[r0][col + 1] = f2tf_f(p1);
                Ps[r0 + 8][col]     = f2tf_f(p2);
                Ps[r0 + 8][col + 1] = f2tf_f(p3);
            }
            l[mg * 2 + 0] += ps0;
            l[mg * 2 + 1] += ps1;
        }
        __syncwarp();

#pragma unroll
        for (int mg = 0; mg < 2; mg++) {
            const int r0 = warp * 32 + mg * 16 + lg;
#pragma unroll
            for (int kk = 0; kk < 8; kk++) {
                const int c = kk * 8 + lt;
                unsigned a[4];
                a[0] = __float_as_uint(Ps[r0][c]);
                a[1] = __float_as_uint(Ps[r0 + 8][c]);
                a[2] = __float_as_uint(Ps[r0][c + 4]);
                a[3] = __float_as_uint(Ps[r0 + 8][c + 4]);
#pragma unroll
                for (int nt = 0; nt < 4; nt++) {
                    unsigned bb[2];
                    bb[0] = __float_as_uint(Vt[nt * 8 + lg][c]);
                    bb[1] = __float_as_uint(Vt[nt * 8 + lg][c + 4]);
                    mma8(o[mg][nt], a, bb);
                }
            }
        }
    }

#pragma unroll
    for (int j = 0; j < 4; j++) {
        l[j] += __shfl_xor_sync(0xffffffffu, l[j], 1);
        l[j] += __shfl_xor_sync(0xffffffffu, l[j], 2);
    }

#pragma unroll
    for (int mg = 0; mg < 2; mg++) {
        float inv0 = 1.0f / l[mg * 2 + 0];
        float inv1 = 1.0f / l[mg * 2 + 1];
        int q0 = qt * 128 + warp * 32 + mg * 16 + lg;
        float* op = out + (size_t)(b * LL + q0) * DD + h * 32;
#pragma unroll
        for (int nt = 0; nt < 4; nt++) {
            int col = nt * 8 + (lt << 1);
            *(float2*)(op + col) = make_float2(o[mg][nt][0] * inv0, o[mg][nt][1] * inv0);
            *(float2*)(op + 8 * DD + col) = make_float2(o[mg][nt][2] * inv1, o[mg][nt][3] * inv1);
        }
    }
}

// ---------------- host orchestration ----------------
extern "C" void kernel_launch(void* const* d_in, const int* in_sizes, int n_in,
                              void* d_out, int out_size)
{
    const float* x        = (const float*)d_in[0];
    const int*   ei       = (const int*)  d_in[1];
    const float* gat_W0   = (const float*)d_in[3];
    const float* gat_W12  = (const float*)d_in[4];
    const float* att_src  = (const float*)d_in[5];
    const float* att_dst  = (const float*)d_in[6];
    const float* gat_bias = (const float*)d_in[7];
    const float* qkv_w    = (const float*)d_in[8];
    const float* qkv_b    = (const float*)d_in[9];
    const float* out_w    = (const float*)d_in[10];
    const float* out_b    = (const float*)d_in[11];
    const float* ln1_w    = (const float*)d_in[12];
    const float* ln1_b    = (const float*)d_in[13];
    const float* ln2_w    = (const float*)d_in[14];
    const float* ln2_b    = (const float*)d_in[15];
    const float* ff1_w    = (const float*)d_in[16];
    const float* ff1_b    = (const float*)d_in[17];
    const float* ff2_w    = (const float*)d_in[18];
    const float* ff2_b    = (const float*)d_in[19];
    const float* pred_w   = (const float*)d_in[20];
    const float* pred_b   = (const float*)d_in[21];

    const int E = in_sizes[1] / 2;
    const int Etot = E + NN;
    const int* src = ei;
    const int* dst = ei + E;

    float *hl, *h0, *h1, *as_, *ad_, *pe, *qkv, *attn, *ff, *wr;
    cudaGetSymbolAddress((void**)&hl,   g_hl);
    cudaGetSymbolAddress((void**)&h0,   g_h0);
    cudaGetSymbolAddress((void**)&h1,   g_h1);
    cudaGetSymbolAddress((void**)&as_,  g_as);
    cudaGetSymbolAddress((void**)&ad_,  g_ad);
    cudaGetSymbolAddress((void**)&pe,   g_pe);
    cudaGetSymbolAddress((void**)&qkv,  g_qkv);
    cudaGetSymbolAddress((void**)&attn, g_attn);
    cudaGetSymbolAddress((void**)&ff,   g_ff);
    cudaGetSymbolAddress((void**)&wr,   g_wr);

    float* W0r  = wr;
    float* W12r = W0r  + W0_N;
    float* qwr  = W12r + W12_N;
    float* owr  = qwr  + QW_N;
    float* f1r  = owr  + OW_N;
    float* f2r  = f1r  + F1_N;

    cudaFuncSetAttribute(tgemm_kernel<1>, cudaFuncAttributeMaxDynamicSharedMemorySize, TG_SMEM2);
    cudaFuncSetAttribute(tgemm_kernel<2>, cudaFuncAttributeMaxDynamicSharedMemorySize, TG_SMEM2);
    cudaFuncSetAttribute(tgemm_kernel<3>, cudaFuncAttributeMaxDynamicSharedMemorySize, TG_SMEM2);
    cudaFuncSetAttribute(tgemm_ln_kernel<0>, cudaFuncAttributeMaxDynamicSharedMemorySize, TL_SMEM3);
    cudaFuncSetAttribute(tgemm_ln_kernel<1>, cudaFuncAttributeMaxDynamicSharedMemorySize, TL_SMEM3);
    cudaFuncSetAttribute(attn_mma_kernel, cudaFuncAttributeMaxDynamicSharedMemorySize, AT_SMEM);

    // pre-round all weights to tf32 (rna) + zero g_deg, one launch
    round_all_kernel<<<(WR_N / 4 + 255) / 256, 256>>>(gat_W0, gat_W12, qkv_w, out_w,
                                                      ff1_w, ff2_w, wr);

    const int eb = (Etot + 255) / 256;

    // CSR build (once)
    csr_hist_kernel<<<eb, 256>>>(dst, E, Etot);
    csr_scan_kernel<<<1, 1024>>>();
    csr_fill_kernel<<<eb, 256>>>(src, dst, E, Etot);

    auto gat_layer = [&](const float* in, int Din, const float* W,
                         const float* atts, const float* attd, const float* bias,
                         float* outp) {
        tgemm_kernel<3><<<dim3(DD / 128, NN / 128), 256, TG_SMEM2>>>(
            in, W, nullptr, hl, NN, DD, Din, atts, attd, as_, ad_);
        gat_edge_p_kernel<<<eb, 256>>>(Etot, as_, ad_, pe);
        gat_gather_kernel<<<NN, 256>>>(hl, pe, bias, outp);
    };

    gat_layer(x,  INC, W0r,             att_src,           att_dst,           gat_bias,          h0);
    gat_layer(h0, DD,  W12r,            att_src + HH * CC, att_dst + HH * CC, gat_bias + DD,     h1);
    gat_layer(h1, DD,  W12r + DD * DD,  att_src + 2*HH*CC, att_dst + 2*HH*CC, gat_bias + 2 * DD, h0);

    for (int l = 0; l < 2; l++) {
        const float* qw  = qwr + (size_t)l * 3 * DD * DD;
        const float* qb  = qkv_b + l * 3 * DD;
        const float* ow  = owr + (size_t)l * DD * DD;
        const float* ob  = out_b + l * DD;
        const float* l1w = ln1_w + l * DD, * l1b = ln1_b + l * DD;
        const float* l2w = ln2_w + l * DD, * l2b = ln2_b + l * DD;
        const float* f1w = f1r + (size_t)l * DFF * DD;
        const float* f1b = ff1_b + l * DFF;
        const float* f2w = f2r + (size_t)l * DD * DFF;
        const float* f2b = ff2_b + l * DD;

        tgemm_kernel<1><<<dim3(3 * DD / 128, NN / 128), 256, TG_SMEM2>>>(
            h0, qw, qb, qkv, NN, 3 * DD, DD, nullptr, nullptr, nullptr, nullptr);
        attn_mma_kernel<<<dim3(BB * HH, LL / 128), 128, AT_SMEM>>>(qkv, attn);
        tgemm_ln_kernel<0><<<dim3(1, NN / 64), 256, TL_SMEM3>>>(
            attn, ow, ob, h0, l1w, l1b, h1, NN, DD, nullptr, nullptr, nullptr);
        tgemm_kernel<2><<<dim3(DFF / 128, NN / 128), 256, TG_SMEM2>>>(
            h1, f1w, f1b, ff, NN, DFF, DD, nullptr, nullptr, nullptr, nullptr);
        if (l == 0) {
            tgemm_ln_kernel<0><<<dim3(1, NN / 64), 256, TL_SMEM3>>>(
                ff, f2w, f2b, h1, l2w, l2b, h0, NN, DFF, nullptr, nullptr, nullptr);
        } else {
            tgemm_ln_kernel<1><<<dim3(1, NN / 64), 256, TL_SMEM3>>>(
                ff, f2w, f2b, h1, l2w, l2b, h0, NN, DFF, pred_w, pred_b, (float*)d_out);
        }
    }
}